// round 13
// baseline (speedup 1.0000x reference)
#include <cuda_runtime.h>
#include <cuda_bf16.h>
#include <math.h>
#include <stdint.h>

// ---------------- problem constants ----------------
#define NB 16
#define NS 25
#define NQ 15
#define NWAY 5
#define NIMG 640            // 400 support + 240 query
#define HL 32
#define DEMB 1600           // 5*5*64
#define GATES 128           // 4*HL

// ---------------- scratch (device globals; no allocations allowed) ----------------
__device__ float g_buf1[640 * 42 * 42 * 64];   // after layer1 pool (fp32)
__device__ float g_buf2[640 * 21 * 21 * 64];   // after layer2 pool
__device__ float g_buf3[640 * 10 * 10 * 64];   // after layer3 pool
__device__ float g_emb [640 * DEMB];           // embeddings (5*5*64)
__device__ float g_xwkf[640 * GATES];
__device__ float g_xwkb[640 * GATES];
__device__ float g_sf[NS * NB * HL];
__device__ float g_sb[NS * NB * HL];
__device__ float g_qf[NQ * NB * HL];
__device__ float g_qb[NQ * NB * HL];

// weight fragments for mma.sync m16n8k16: layers 2-4: [tap][kstep][ntile][lane]
// uint4 = {bhi0, bhi1, blo0, blo1}  (9*4*8*32 = 9216 uint4 = 144KB per layer)
__device__ uint4 g_wfrag[3][9216];
// layer 1 fragments: [kstep(2)][ntile(8)][lane(32)] = 512 uint4 (K=27 padded to 32)
__device__ uint4 g_wfrag1[512];

// ---------------- bf16 split helpers ----------------
__device__ __forceinline__ uint32_t pack_hi2(float x0, float x1) {
    __nv_bfloat162 p = __halves2bfloat162(__float2bfloat16(x0), __float2bfloat16(x1));
    return *reinterpret_cast<uint32_t*>(&p);
}
__device__ __forceinline__ uint32_t pack_lo2(float x0, float x1) {
    __nv_bfloat16 h0 = __float2bfloat16(x0);
    __nv_bfloat16 h1 = __float2bfloat16(x1);
    __nv_bfloat162 p = __halves2bfloat162(__float2bfloat16(x0 - __bfloat162float(h0)),
                                          __float2bfloat16(x1 - __bfloat162float(h1)));
    return *reinterpret_cast<uint32_t*>(&p);
}

#define MMA_BF16(d, a, b0, b1) \
    asm volatile("mma.sync.aligned.m16n8k16.row.col.f32.bf16.bf16.f32 " \
        "{%0,%1,%2,%3}, {%4,%5,%6,%7}, {%8,%9}, {%0,%1,%2,%3};" \
        : "+f"((d)[0]), "+f"((d)[1]), "+f"((d)[2]), "+f"((d)[3]) \
        : "r"((a)[0]), "r"((a)[1]), "r"((a)[2]), "r"((a)[3]), "r"(b0), "r"(b1))

// ---------------- weight fragment prep (layers 2-4) ----------------
__global__ void prep_wfrag(const float* __restrict__ w, uint4* __restrict__ dst)
{
    int i = blockIdx.x * 256 + threadIdx.x;
    if (i >= 9216) return;
    int lane = i & 31;
    int nt   = (i >> 5) & 7;
    int ks   = (i >> 8) & 3;
    int tap  = i >> 10;
    int g = lane >> 2, l4 = lane & 3;
    int n  = nt * 8 + g;
    int k0 = ks * 16 + l4 * 2;
    float x00 = w[(tap * 64 + k0 + 0) * 64 + n];
    float x01 = w[(tap * 64 + k0 + 1) * 64 + n];
    float x10 = w[(tap * 64 + k0 + 8) * 64 + n];
    float x11 = w[(tap * 64 + k0 + 9) * 64 + n];
    uint4 o;
    o.x = pack_hi2(x00, x01);
    o.y = pack_hi2(x10, x11);
    o.z = pack_lo2(x00, x01);
    o.w = pack_lo2(x10, x11);
    dst[i] = o;
}

// ---------------- weight fragment prep (layer 1, K=27 padded to 32) ----------------
__global__ void prep_wfrag1(const float* __restrict__ w, uint4* __restrict__ dst)
{
    int i = blockIdx.x * 256 + threadIdx.x;
    if (i >= 512) return;
    int lane = i & 31;
    int nt   = (i >> 5) & 7;
    int ks   = i >> 8;
    int g = lane >> 2, l4 = lane & 3;
    int n  = nt * 8 + g;
    int k0 = ks * 16 + l4 * 2;
    float x[4];
#pragma unroll
    for (int j = 0; j < 4; j++) {
        int k = k0 + (j >> 1) * 8 + (j & 1);
        x[j] = (k < 27) ? w[k * 64 + n] : 0.f;   // flat [tap*3+cin][64]
    }
    uint4 o;
    o.x = pack_hi2(x[0], x[1]);
    o.y = pack_hi2(x[2], x[3]);
    o.z = pack_lo2(x[0], x[1]);
    o.w = pack_lo2(x[2], x[3]);
    dst[i] = o;
}

// ---------------- layer 1: tensor conv via padded im2col (fp32 out) ----------------
__global__ void __launch_bounds__(128)
conv1_tensor(const float* __restrict__ in_sup,
             const float* __restrict__ in_qry,
             const uint4* __restrict__ wfrag1,
             const float* __restrict__ cb, const float* __restrict__ gm,
             const float* __restrict__ bt, const float* __restrict__ mn,
             const float* __restrict__ vr,
             float* __restrict__ out)     // [640][42][42][64] fp32
{
    __shared__ float sWin[540];          // 18 x 10 x 3 fp32 window
    __shared__ uint4 sB[512];
    __shared__ float sS[64], sT[64];

    const int tid = threadIdx.x;
    const int wrp = tid >> 5;
    const int lane = tid & 31;
    const int g = lane >> 2, l4 = lane & 3;

    for (int i = tid; i < 512; i += 128) sB[i] = __ldg(wfrag1 + i);
    if (tid < 64) {
        float s = gm[tid] * rsqrtf(vr[tid] + 1e-3f);
        sS[tid] = s;
        sT[tid] = (cb[tid] - mn[tid]) * s + bt[tid];
    }
    __syncthreads();

    const int TR = 6, TC = 11, tpi = TR * TC;
    const int ntiles = NIMG * tpi;

    for (int tile = blockIdx.x; tile < ntiles; tile += gridDim.x) {
        const int img = tile / tpi;
        const int rem = tile - img * tpi;
        const int r0  = (rem / TC) * 16;
        const int c0  = (rem % TC) * 8;
        const float* base = (img < 400) ? (in_sup + (size_t)img * 84 * 84 * 3)
                                        : (in_qry + (size_t)(img - 400) * 84 * 84 * 3);

        for (int e = tid; e < 540; e += 128) {
            int cell = e / 3, ch = e - 3 * cell;
            int wr = cell / 10, wc = cell - 10 * wr;
            int gr = r0 - 1 + wr, gc = c0 - 1 + wc;
            float v = 0.f;
            if (gr >= 0 && gr < 84 && gc >= 0 && gc < 84)
                v = __ldg(base + ((size_t)gr * 84 + gc) * 3 + ch);
            sWin[e] = v;
        }
        __syncthreads();

        float d[2][8][4];
#pragma unroll
        for (int mt = 0; mt < 2; mt++)
#pragma unroll
            for (int nt = 0; nt < 8; nt++)
#pragma unroll
                for (int j = 0; j < 4; j++) d[mt][nt][j] = 0.f;

        auto l1v = [&](int prow, int k) -> float {
            if (k >= 27) return 0.f;
            int tap = k / 3, ch = k - 3 * tap;
            int ky = tap / 3, kx = tap - 3 * ky;
            return sWin[((prow + ky) * 10 + (g + kx)) * 3 + ch];
        };

#pragma unroll
        for (int ks = 0; ks < 2; ks++) {
            uint32_t ah[2][4], al[2][4];
#pragma unroll
            for (int mt = 0; mt < 2; mt++) {
                const int rb = 4 * wrp + 2 * mt;
                const int k0 = ks * 16 + 2 * l4;
                float x00 = l1v(rb,     k0),     x01 = l1v(rb,     k0 + 1);
                float x10 = l1v(rb + 1, k0),     x11 = l1v(rb + 1, k0 + 1);
                float x20 = l1v(rb,     k0 + 8), x21 = l1v(rb,     k0 + 9);
                float x30 = l1v(rb + 1, k0 + 8), x31 = l1v(rb + 1, k0 + 9);
                ah[mt][0] = pack_hi2(x00, x01); al[mt][0] = pack_lo2(x00, x01);
                ah[mt][1] = pack_hi2(x10, x11); al[mt][1] = pack_lo2(x10, x11);
                ah[mt][2] = pack_hi2(x20, x21); al[mt][2] = pack_lo2(x20, x21);
                ah[mt][3] = pack_hi2(x30, x31); al[mt][3] = pack_lo2(x30, x31);
            }
            // B fragments into registers, then term-major MMA stream
            uint4 b[8];
#pragma unroll
            for (int nt = 0; nt < 8; nt++) b[nt] = sB[(ks * 8 + nt) * 32 + lane];
#pragma unroll
            for (int nt = 0; nt < 8; nt++) {
                MMA_BF16(d[0][nt], ah[0], b[nt].x, b[nt].y);
                MMA_BF16(d[1][nt], ah[1], b[nt].x, b[nt].y);
            }
#pragma unroll
            for (int nt = 0; nt < 8; nt++) {
                MMA_BF16(d[0][nt], al[0], b[nt].x, b[nt].y);
                MMA_BF16(d[1][nt], al[1], b[nt].x, b[nt].y);
            }
#pragma unroll
            for (int nt = 0; nt < 8; nt++) {
                MMA_BF16(d[0][nt], ah[0], b[nt].z, b[nt].w);
                MMA_BF16(d[1][nt], ah[1], b[nt].z, b[nt].w);
            }
        }

        // BN + ReLU + 2x2 pool + fp32 store
#pragma unroll
        for (int mt = 0; mt < 2; mt++) {
            const int pr = (r0 >> 1) + 2 * wrp + mt;
            const int pc = (c0 >> 1) + (g >> 1);
            const bool valid = ((g & 1) == 0) && pr < 42 && pc < 42;
            float* obase = out + (((size_t)img * 42 + pr) * 42 + pc) * 64;
#pragma unroll
            for (int nt = 0; nt < 8; nt++) {
                const int oc = nt * 8 + l4 * 2;
                float s0 = sS[oc], s1 = sS[oc + 1];
                float t0 = sT[oc], t1 = sT[oc + 1];
                float v0 = fmaxf(fmaf(d[0][nt][0] * 0.f + d[mt][nt][0], s0, t0), 0.f);
                float v1 = fmaxf(fmaf(d[mt][nt][1], s1, t1), 0.f);
                float v2 = fmaxf(fmaf(d[mt][nt][2], s0, t0), 0.f);
                float v3 = fmaxf(fmaf(d[mt][nt][3], s1, t1), 0.f);
                v0 = fmaxf(fmaf(d[mt][nt][0], s0, t0), 0.f);
                float m0 = fmaxf(v0, v2);
                float m1 = fmaxf(v1, v3);
                m0 = fmaxf(m0, __shfl_xor_sync(0xffffffffu, m0, 4));
                m1 = fmaxf(m1, __shfl_xor_sync(0xffffffffu, m1, 4));
                if (valid) *(float2*)(obase + oc) = make_float2(m0, m1);
            }
        }
        __syncthreads();
    }
}

// ---------------- tensor conv (layers 2-4): term-major MMA stream ----------------
#define SMW   0            // weight frags: 147456 B
#define SMAH  147456       // activation hi: 180 cells * 36 words * 4 = 25920 B
#define SMAL  173376       // activation lo: 25920 B
#define SMC   199296       // BN consts: 512 B
#define CONV_SMEM 199808

__global__ void __launch_bounds__(128, 1)
conv_tensor(const float* __restrict__ in,
            const uint4* __restrict__ wfrag,
            const float* __restrict__ cb, const float* __restrict__ gm,
            const float* __restrict__ bt, const float* __restrict__ mn,
            const float* __restrict__ vr,
            float* __restrict__ out,
            int H, int PH, int TR, int TC, int ntiles)
{
    extern __shared__ __align__(16) char smem[];
    const int tid = threadIdx.x;
    const int wrp = tid >> 5;
    const int lane = tid & 31;
    const int g = lane >> 2, l4 = lane & 3;

    {
        uint4* dw = (uint4*)(smem + SMW);
        for (int i = tid; i < 9216; i += 128) dw[i] = wfrag[i];
    }
    if (tid < 64) {
        float s = gm[tid] * rsqrtf(vr[tid] + 1e-3f);
        float t = (cb[tid] - mn[tid]) * s + bt[tid];
        ((float*)(smem + SMC))[tid] = s;
        ((float*)(smem + SMC + 256))[tid] = t;
    }
    __syncthreads();

    uint32_t* sAh = (uint32_t*)(smem + SMAH);
    uint32_t* sAl = (uint32_t*)(smem + SMAL);
    const uint4* sW = (const uint4*)(smem + SMW);
    const float* sS = (const float*)(smem + SMC);
    const float* sT = (const float*)(smem + SMC + 256);
    const int tpi = TR * TC;

    for (int tile = blockIdx.x; tile < ntiles; tile += gridDim.x) {
        const int img  = tile / tpi;
        const int rem  = tile - img * tpi;
        const int r0   = (rem / TC) * 16;
        const int c0   = (rem % TC) * 8;
        const float* ibase = in + (size_t)img * H * H * 64;

        // ---- stage 18x10x64 window as bf16 hi/lo (pair-stride 36 words) ----
        for (int e = tid; e < 180 * 32; e += 128) {
            int pair = e & 31;
            int cell = e >> 5;
            int wr = cell / 10, wc = cell - 10 * wr;
            int gr = r0 - 1 + wr, gc = c0 - 1 + wc;
            float x0 = 0.f, x1 = 0.f;
            if (gr >= 0 && gr < H && gc >= 0 && gc < H) {
                float2 v = *(const float2*)(ibase + ((size_t)(gr * H + gc) << 6) + 2 * pair);
                x0 = v.x; x1 = v.y;
            }
            sAh[cell * 36 + pair] = pack_hi2(x0, x1);
            sAl[cell * 36 + pair] = pack_lo2(x0, x1);
        }
        __syncthreads();

        float d[2][8][4];
#pragma unroll
        for (int mt = 0; mt < 2; mt++)
#pragma unroll
            for (int nt = 0; nt < 8; nt++)
#pragma unroll
                for (int j = 0; j < 4; j++) d[mt][nt][j] = 0.f;

        for (int tap = 0; tap < 9; tap++) {
            const int ky = tap / 3, kx = tap - 3 * (tap / 3);
#pragma unroll
            for (int ks = 0; ks < 4; ks++) {
                uint32_t ah[2][4], al[2][4];
#pragma unroll
                for (int mt = 0; mt < 2; mt++) {
                    const int rb = 4 * wrp + 2 * mt;
                    const int cell0 = (rb + ky) * 10 + (g + kx);
                    const int cell1 = cell0 + 10;
                    const int p0 = ks * 8 + l4;
                    ah[mt][0] = sAh[cell0 * 36 + p0];
                    ah[mt][1] = sAh[cell1 * 36 + p0];
                    ah[mt][2] = sAh[cell0 * 36 + p0 + 4];
                    ah[mt][3] = sAh[cell1 * 36 + p0 + 4];
                    al[mt][0] = sAl[cell0 * 36 + p0];
                    al[mt][1] = sAl[cell1 * 36 + p0];
                    al[mt][2] = sAl[cell0 * 36 + p0 + 4];
                    al[mt][3] = sAl[cell1 * 36 + p0 + 4];
                }
                // B fragments into registers, then term-major MMA stream
                const uint4* wb = sW + ((tap * 4 + ks) * 8) * 32 + lane;
                uint4 b[8];
#pragma unroll
                for (int nt = 0; nt < 8; nt++) b[nt] = wb[nt * 32];
#pragma unroll
                for (int nt = 0; nt < 8; nt++) {
                    MMA_BF16(d[0][nt], ah[0], b[nt].x, b[nt].y);   // hi*hi
                    MMA_BF16(d[1][nt], ah[1], b[nt].x, b[nt].y);
                }
#pragma unroll
                for (int nt = 0; nt < 8; nt++) {
                    MMA_BF16(d[0][nt], al[0], b[nt].x, b[nt].y);   // lo*hi
                    MMA_BF16(d[1][nt], al[1], b[nt].x, b[nt].y);
                }
#pragma unroll
                for (int nt = 0; nt < 8; nt++) {
                    MMA_BF16(d[0][nt], ah[0], b[nt].z, b[nt].w);   // hi*lo
                    MMA_BF16(d[1][nt], ah[1], b[nt].z, b[nt].w);
                }
            }
        }

        // ---- BN + ReLU + 2x2 maxpool + store ----
#pragma unroll
        for (int mt = 0; mt < 2; mt++) {
            const int pr = (r0 >> 1) + 2 * wrp + mt;
            const int pc = (c0 >> 1) + (g >> 1);
            const bool valid = ((g & 1) == 0) && pr < PH && pc < PH;
            float* obase = out + (((size_t)img * PH + pr) * PH + pc) * 64;
#pragma unroll
            for (int nt = 0; nt < 8; nt++) {
                const int oc = nt * 8 + l4 * 2;
                float s0 = sS[oc], s1 = sS[oc + 1];
                float t0 = sT[oc], t1 = sT[oc + 1];
                float v0 = fmaxf(fmaf(d[mt][nt][0], s0, t0), 0.f);
                float v1 = fmaxf(fmaf(d[mt][nt][1], s1, t1), 0.f);
                float v2 = fmaxf(fmaf(d[mt][nt][2], s0, t0), 0.f);
                float v3 = fmaxf(fmaf(d[mt][nt][3], s1, t1), 0.f);
                float m0 = fmaxf(v0, v2);
                float m1 = fmaxf(v1, v3);
                m0 = fmaxf(m0, __shfl_xor_sync(0xffffffffu, m0, 4));
                m1 = fmaxf(m1, __shfl_xor_sync(0xffffffffu, m1, 4));
                if (valid) *(float2*)(obase + oc) = make_float2(m0, m1);
            }
        }
        __syncthreads();
    }
}

// ---------------- x @ Wk + bias ----------------
__global__ void xwk_gemm(const float* __restrict__ emb,
                         const float* __restrict__ Wk,
                         const float* __restrict__ bias,
                         float* __restrict__ outp)
{
    int idx = blockIdx.x * blockDim.x + threadIdx.x;
    if (idx >= NIMG * GATES) return;
    int u = idx & (GATES - 1);
    int n = idx >> 7;
    const float* e = emb + (size_t)n * DEMB;
    float acc = __ldg(bias + u);
#pragma unroll 4
    for (int k = 0; k < DEMB; k += 4) {
        float4 ev = *reinterpret_cast<const float4*>(e + k);
        acc = fmaf(ev.x, __ldg(Wk + (size_t)(k + 0) * GATES + u), acc);
        acc = fmaf(ev.y, __ldg(Wk + (size_t)(k + 1) * GATES + u), acc);
        acc = fmaf(ev.z, __ldg(Wk + (size_t)(k + 2) * GATES + u), acc);
        acc = fmaf(ev.w, __ldg(Wk + (size_t)(k + 3) * GATES + u), acc);
    }
    outp[idx] = acc;
}

// ---------------- LSTM chains over the BATCH axis ----------------
__device__ __forceinline__ float sigm(float x) { return 1.f / (1.f + expf(-x)); }

__global__ void lstm_chains(const float* __restrict__ xwkf,
                            const float* __restrict__ xwkb,
                            const float* __restrict__ Wrf,
                            const float* __restrict__ Wrb,
                            float* __restrict__ sf, float* __restrict__ sb2,
                            float* __restrict__ qf, float* __restrict__ qb)
{
    __shared__ float wr[HL * GATES];
    __shared__ float h[HL], c[HL], z[GATES];

    const int u     = threadIdx.x;
    const int chain = blockIdx.x;
    const int dir   = blockIdx.y;

    const float* xwk = dir ? xwkb : xwkf;
    const float* Wr  = dir ? Wrb  : Wrf;
    float* outp = (chain < NS) ? (dir ? sb2 : sf) : (dir ? qb : qf);
    const int cpos = (chain < NS) ? chain : (chain - NS);

#pragma unroll
    for (int k = 0; k < HL; k++) wr[k * GATES + u] = Wr[k * GATES + u];
    if (u < HL) { h[u] = 0.f; c[u] = 0.f; }
    __syncthreads();

    for (int t = 0; t < NB; t++) {
        const int b = dir ? (NB - 1 - t) : t;
        const int row = (chain < NS) ? (b * NS + cpos) : (400 + b * NQ + cpos);
        float acc = __ldg(xwk + (size_t)row * GATES + u);
#pragma unroll
        for (int k = 0; k < HL; k++) acc = fmaf(h[k], wr[k * GATES + u], acc);
        z[u] = acc;
        __syncthreads();
        if (u < HL) {
            float zi = z[u], zf = z[HL + u], zg = z[2 * HL + u], zo = z[3 * HL + u];
            float cc = sigm(zf) * c[u] + sigm(zi) * tanhf(zg);
            float hh = sigm(zo) * tanhf(cc);
            c[u] = cc; h[u] = hh;
            outp[(cpos * NB + b) * HL + u] = hh;
        }
        __syncthreads();
    }
}

// ---------------- attention readout + CE + accuracy ----------------
__global__ void readout(const float* __restrict__ sf, const float* __restrict__ sb2,
                        const float* __restrict__ qf, const float* __restrict__ qb,
                        const int* __restrict__ ysup, const int* __restrict__ yqry,
                        float* __restrict__ out)
{
    __shared__ float ce_sm[NQ * NB];
    __shared__ float corr_sm[NQ * NB];
    const int t = threadIdx.x;

    if (t < NQ * NB) {
        const int q = t / NB, b = t % NB;
        float vf[HL], vb[HL];
#pragma unroll
        for (int j = 0; j < HL; j++) {
            vf[j] = qf[(q * NB + b) * HL + j];
            vb[j] = qb[(q * NB + b) * HL + j];
        }
        float scores[NS];
        float mx = -1e30f;
        for (int s = 0; s < NS; s++) {
            float dot = 0.f, nrm = 0.f;
#pragma unroll
            for (int j = 0; j < HL; j++) {
                float a = sf[(s * NB + b) * HL + j];
                dot = fmaf(vf[j], a, dot); nrm = fmaf(a, a, nrm);
            }
#pragma unroll
            for (int j = 0; j < HL; j++) {
                float a = sb2[(s * NB + b) * HL + j];
                dot = fmaf(vb[j], a, dot); nrm = fmaf(a, a, nrm);
            }
            float sc = dot * rsqrtf(fmaxf(nrm, 1e-10f));
            scores[s] = sc; mx = fmaxf(mx, sc);
        }
        float sum = 0.f;
        for (int s = 0; s < NS; s++) { scores[s] = expf(scores[s] - mx); sum += scores[s]; }
        float inv = 1.f / sum;
        float preds[NWAY] = {0.f, 0.f, 0.f, 0.f, 0.f};
        for (int s = 0; s < NS; s++) preds[ysup[b * NS + s]] += scores[s] * inv;

        float psum = 0.f;
        for (int w = 0; w < NWAY; w++) psum += preds[w];
        const int yq = yqry[b * NQ + q];
        float pv = preds[yq] / psum;
        pv = fminf(fmaxf(pv, 1e-7f), 1.f - 1e-7f);
        ce_sm[t] = -logf(pv);

        int am = 0; float bv = preds[0];
        for (int w = 1; w < NWAY; w++) if (preds[w] > bv) { bv = preds[w]; am = w; }
        corr_sm[t] = (am == yq) ? 1.f : 0.f;
    }
    __syncthreads();
    if (t < NB) {
        float s = 0.f;
        for (int q = 0; q < NQ; q++) s += ce_sm[q * NB + t];
        out[t] = s / (float)NQ;
    }
    if (t == 16) {
        float s = 0.f;
        for (int i = 0; i < NQ * NB; i++) s += corr_sm[i];
        out[16] = s / (float)(NQ * NB);
    }
}

// ---------------- launch ----------------
extern "C" void kernel_launch(void* const* d_in, const int* in_sizes, int n_in,
                              void* d_out, int out_size)
{
    const float* xs = (const float*)d_in[0];
    const float* xq = (const float*)d_in[1];
    const int*   ys = (const int*)  d_in[2];
    const int*   yq = (const int*)  d_in[3];
    const float* w1 = (const float*)d_in[4];
    const float* w2 = (const float*)d_in[5];
    const float* w3 = (const float*)d_in[6];
    const float* w4 = (const float*)d_in[7];
    const float* cb = (const float*)d_in[8];
    const float* gm = (const float*)d_in[9];
    const float* bt = (const float*)d_in[10];
    const float* mn = (const float*)d_in[11];
    const float* vr = (const float*)d_in[12];
    const float* fk = (const float*)d_in[13];
    const float* fr = (const float*)d_in[14];
    const float* fb = (const float*)d_in[15];
    const float* bk = (const float*)d_in[16];
    const float* br = (const float*)d_in[17];
    const float* bb = (const float*)d_in[18];

    float *buf1, *buf2, *buf3, *emb, *xwkf, *xwkb, *sf, *sb, *qf, *qb;
    uint4 *wfrag, *wfrag1;
    cudaGetSymbolAddress((void**)&buf1, g_buf1);
    cudaGetSymbolAddress((void**)&buf2, g_buf2);
    cudaGetSymbolAddress((void**)&buf3, g_buf3);
    cudaGetSymbolAddress((void**)&emb,  g_emb);
    cudaGetSymbolAddress((void**)&xwkf, g_xwkf);
    cudaGetSymbolAddress((void**)&xwkb, g_xwkb);
    cudaGetSymbolAddress((void**)&sf,   g_sf);
    cudaGetSymbolAddress((void**)&sb,   g_sb);
    cudaGetSymbolAddress((void**)&qf,   g_qf);
    cudaGetSymbolAddress((void**)&qb,   g_qb);
    cudaGetSymbolAddress((void**)&wfrag, g_wfrag);
    cudaGetSymbolAddress((void**)&wfrag1, g_wfrag1);

    cudaFuncSetAttribute(conv_tensor, cudaFuncAttributeMaxDynamicSharedMemorySize, CONV_SMEM);

    // weight fragment prep (tiny)
    prep_wfrag1<<<2, 256>>>(w1, wfrag1);
    prep_wfrag<<<36, 256>>>(w2, wfrag + 0 * 9216);
    prep_wfrag<<<36, 256>>>(w3, wfrag + 1 * 9216);
    prep_wfrag<<<36, 256>>>(w4, wfrag + 2 * 9216);

    // layer 1: tensor path via padded im2col, high-occupancy grid (fp32 out)
    conv1_tensor<<<1184, 128>>>(xs, xq, wfrag1,
        cb + 0, gm + 0, bt + 0, mn + 0, vr + 0, buf1);

    // layers 2-4: mma.sync bf16 tensor path (persistent, grid=148)
    conv_tensor<<<148, 128, CONV_SMEM>>>(buf1, wfrag + 0 * 9216,
        cb + 64,  gm + 64,  bt + 64,  mn + 64,  vr + 64,  buf2, 42, 21, 3, 6, 640 * 18);
    conv_tensor<<<148, 128, CONV_SMEM>>>(buf2, wfrag + 1 * 9216,
        cb + 128, gm + 128, bt + 128, mn + 128, vr + 128, buf3, 21, 10, 2, 3, 640 * 6);
    conv_tensor<<<148, 128, CONV_SMEM>>>(buf3, wfrag + 2 * 9216,
        cb + 192, gm + 192, bt + 192, mn + 192, vr + 192, emb, 10, 5, 1, 2, 640 * 2);

    // FCE input projections
    xwk_gemm<<<(NIMG * GATES + 255) / 256, 256>>>(emb, fk, fb, xwkf);
    xwk_gemm<<<(NIMG * GATES + 255) / 256, 256>>>(emb, bk, bb, xwkb);

    // FCE chains (recurrence over the batch axis)
    lstm_chains<<<dim3(40, 2), GATES>>>(xwkf, xwkb, fr, br, sf, sb, qf, qb);

    // attention + CE + acc
    readout<<<1, 256>>>(sf, sb, qf, qb, ys, yq, (float*)d_out);
}

// round 14
// speedup vs baseline: 1.1419x; 1.1419x over previous
#include <cuda_runtime.h>
#include <cuda_bf16.h>
#include <math.h>
#include <stdint.h>

// ---------------- problem constants ----------------
#define NB 16
#define NS 25
#define NQ 15
#define NWAY 5
#define NIMG 640            // 400 support + 240 query
#define HL 32
#define DEMB 1600           // 5*5*64
#define GATES 128           // 4*HL

// ---------------- scratch (device globals; no allocations allowed) ----------------
// activations between conv layers: bf16 pairs [img][H][W][32] uint32 (hi, lo)
__device__ uint32_t g_b1h[640 * 42 * 42 * 32];
__device__ uint32_t g_b1l[640 * 42 * 42 * 32];
__device__ uint32_t g_b2h[640 * 21 * 21 * 32];
__device__ uint32_t g_b2l[640 * 21 * 21 * 32];
__device__ uint32_t g_b3h[640 * 10 * 10 * 32];
__device__ uint32_t g_b3l[640 * 10 * 10 * 32];
__device__ float g_emb [640 * DEMB];           // embeddings (5*5*64) fp32
__device__ float g_xwkf[640 * GATES];
__device__ float g_xwkb[640 * GATES];
__device__ float g_sf[NS * NB * HL];
__device__ float g_sb[NS * NB * HL];
__device__ float g_qf[NQ * NB * HL];
__device__ float g_qb[NQ * NB * HL];

// weight fragments for mma.sync m16n8k16: layers 2-4: [tap][kstep][ntile][lane]
// uint4 = {bhi0, bhi1, blo0, blo1}  (9*4*8*32 = 9216 uint4 = 144KB per layer)
__device__ uint4 g_wfrag[3][9216];
// layer 1 fragments: [kstep(2)][ntile(8)][lane(32)] = 512 uint4 (K=27 padded to 32)
__device__ uint4 g_wfrag1[512];

// ---------------- bf16 split helpers ----------------
__device__ __forceinline__ uint32_t pack_hi2(float x0, float x1) {
    __nv_bfloat162 p = __halves2bfloat162(__float2bfloat16(x0), __float2bfloat16(x1));
    return *reinterpret_cast<uint32_t*>(&p);
}
__device__ __forceinline__ uint32_t pack_lo2(float x0, float x1) {
    __nv_bfloat16 h0 = __float2bfloat16(x0);
    __nv_bfloat16 h1 = __float2bfloat16(x1);
    __nv_bfloat162 p = __halves2bfloat162(__float2bfloat16(x0 - __bfloat162float(h0)),
                                          __float2bfloat16(x1 - __bfloat162float(h1)));
    return *reinterpret_cast<uint32_t*>(&p);
}

#define MMA_BF16(d, a, b0, b1) \
    asm volatile("mma.sync.aligned.m16n8k16.row.col.f32.bf16.bf16.f32 " \
        "{%0,%1,%2,%3}, {%4,%5,%6,%7}, {%8,%9}, {%0,%1,%2,%3};" \
        : "+f"((d)[0]), "+f"((d)[1]), "+f"((d)[2]), "+f"((d)[3]) \
        : "r"((a)[0]), "r"((a)[1]), "r"((a)[2]), "r"((a)[3]), "r"(b0), "r"(b1))

// ---------------- weight fragment prep (layers 2-4) ----------------
__global__ void prep_wfrag(const float* __restrict__ w, uint4* __restrict__ dst)
{
    int i = blockIdx.x * 256 + threadIdx.x;
    if (i >= 9216) return;
    int lane = i & 31;
    int nt   = (i >> 5) & 7;
    int ks   = (i >> 8) & 3;
    int tap  = i >> 10;
    int g = lane >> 2, l4 = lane & 3;
    int n  = nt * 8 + g;
    int k0 = ks * 16 + l4 * 2;
    float x00 = w[(tap * 64 + k0 + 0) * 64 + n];
    float x01 = w[(tap * 64 + k0 + 1) * 64 + n];
    float x10 = w[(tap * 64 + k0 + 8) * 64 + n];
    float x11 = w[(tap * 64 + k0 + 9) * 64 + n];
    uint4 o;
    o.x = pack_hi2(x00, x01);
    o.y = pack_hi2(x10, x11);
    o.z = pack_lo2(x00, x01);
    o.w = pack_lo2(x10, x11);
    dst[i] = o;
}

// ---------------- weight fragment prep (layer 1, K=27 padded to 32) ----------------
__global__ void prep_wfrag1(const float* __restrict__ w, uint4* __restrict__ dst)
{
    int i = blockIdx.x * 256 + threadIdx.x;
    if (i >= 512) return;
    int lane = i & 31;
    int nt   = (i >> 5) & 7;
    int ks   = i >> 8;
    int g = lane >> 2, l4 = lane & 3;
    int n  = nt * 8 + g;
    int k0 = ks * 16 + l4 * 2;
    float x[4];
#pragma unroll
    for (int j = 0; j < 4; j++) {
        int k = k0 + (j >> 1) * 8 + (j & 1);
        x[j] = (k < 27) ? w[k * 64 + n] : 0.f;   // flat [tap*3+cin][64]
    }
    uint4 o;
    o.x = pack_hi2(x[0], x[1]);
    o.y = pack_hi2(x[2], x[3]);
    o.z = pack_lo2(x[0], x[1]);
    o.w = pack_lo2(x[2], x[3]);
    dst[i] = o;
}

// ---------------- layer 1: tensor conv via padded im2col (pair out) ------------
// High-occupancy grid (no forced 1 CTA/SM). Tile = 16x8 conv px at 84x84.
__global__ void __launch_bounds__(128)
conv1_tensor(const float* __restrict__ in_sup,
             const float* __restrict__ in_qry,
             const uint4* __restrict__ wfrag1,
             const float* __restrict__ cb, const float* __restrict__ gm,
             const float* __restrict__ bt, const float* __restrict__ mn,
             const float* __restrict__ vr,
             uint32_t* __restrict__ outh, uint32_t* __restrict__ outl)
{
    __shared__ float sWin[540];          // 18 x 10 x 3 fp32 window
    __shared__ uint4 sB[512];
    __shared__ float sS[64], sT[64];

    const int tid = threadIdx.x;
    const int wrp = tid >> 5;
    const int lane = tid & 31;
    const int g = lane >> 2, l4 = lane & 3;

    for (int i = tid; i < 512; i += 128) sB[i] = __ldg(wfrag1 + i);
    if (tid < 64) {
        float s = gm[tid] * rsqrtf(vr[tid] + 1e-3f);
        sS[tid] = s;
        sT[tid] = (cb[tid] - mn[tid]) * s + bt[tid];
    }
    __syncthreads();

    const int TR = 6, TC = 11, tpi = TR * TC;
    const int ntiles = NIMG * tpi;

    for (int tile = blockIdx.x; tile < ntiles; tile += gridDim.x) {
        const int img = tile / tpi;
        const int rem = tile - img * tpi;
        const int r0  = (rem / TC) * 16;
        const int c0  = (rem % TC) * 8;
        const float* base = (img < 400) ? (in_sup + (size_t)img * 84 * 84 * 3)
                                        : (in_qry + (size_t)(img - 400) * 84 * 84 * 3);

        for (int e = tid; e < 540; e += 128) {
            int cell = e / 3, ch = e - 3 * cell;
            int wr = cell / 10, wc = cell - 10 * wr;
            int gr = r0 - 1 + wr, gc = c0 - 1 + wc;
            float v = 0.f;
            if (gr >= 0 && gr < 84 && gc >= 0 && gc < 84)
                v = __ldg(base + ((size_t)gr * 84 + gc) * 3 + ch);
            sWin[e] = v;
        }
        __syncthreads();

        float d[2][8][4];
#pragma unroll
        for (int mt = 0; mt < 2; mt++)
#pragma unroll
            for (int nt = 0; nt < 8; nt++)
#pragma unroll
                for (int j = 0; j < 4; j++) d[mt][nt][j] = 0.f;

        auto l1v = [&](int prow, int k) -> float {
            if (k >= 27) return 0.f;
            int tap = k / 3, ch = k - 3 * tap;
            int ky = tap / 3, kx = tap - 3 * ky;
            return sWin[((prow + ky) * 10 + (g + kx)) * 3 + ch];
        };

#pragma unroll
        for (int ks = 0; ks < 2; ks++) {
            uint32_t ah[2][4], al[2][4];
#pragma unroll
            for (int mt = 0; mt < 2; mt++) {
                const int rb = 4 * wrp + 2 * mt;
                const int k0 = ks * 16 + 2 * l4;
                float x00 = l1v(rb,     k0),     x01 = l1v(rb,     k0 + 1);
                float x10 = l1v(rb + 1, k0),     x11 = l1v(rb + 1, k0 + 1);
                float x20 = l1v(rb,     k0 + 8), x21 = l1v(rb,     k0 + 9);
                float x30 = l1v(rb + 1, k0 + 8), x31 = l1v(rb + 1, k0 + 9);
                ah[mt][0] = pack_hi2(x00, x01); al[mt][0] = pack_lo2(x00, x01);
                ah[mt][1] = pack_hi2(x10, x11); al[mt][1] = pack_lo2(x10, x11);
                ah[mt][2] = pack_hi2(x20, x21); al[mt][2] = pack_lo2(x20, x21);
                ah[mt][3] = pack_hi2(x30, x31); al[mt][3] = pack_lo2(x30, x31);
            }
            uint4 b[8];
#pragma unroll
            for (int nt = 0; nt < 8; nt++) b[nt] = sB[(ks * 8 + nt) * 32 + lane];
#pragma unroll
            for (int nt = 0; nt < 8; nt++) {
                MMA_BF16(d[0][nt], ah[0], b[nt].x, b[nt].y);
                MMA_BF16(d[1][nt], ah[1], b[nt].x, b[nt].y);
            }
#pragma unroll
            for (int nt = 0; nt < 8; nt++) {
                MMA_BF16(d[0][nt], al[0], b[nt].x, b[nt].y);
                MMA_BF16(d[1][nt], al[1], b[nt].x, b[nt].y);
            }
#pragma unroll
            for (int nt = 0; nt < 8; nt++) {
                MMA_BF16(d[0][nt], ah[0], b[nt].z, b[nt].w);
                MMA_BF16(d[1][nt], ah[1], b[nt].z, b[nt].w);
            }
        }

        // BN + ReLU + 2x2 pool + pair store
#pragma unroll
        for (int mt = 0; mt < 2; mt++) {
            const int pr = (r0 >> 1) + 2 * wrp + mt;
            const int pc = (c0 >> 1) + (g >> 1);
            const bool valid = ((g & 1) == 0) && pr < 42 && pc < 42;
            const uint32_t obase = ((uint32_t)img * 42 + pr) * 42 + pc;
#pragma unroll
            for (int nt = 0; nt < 8; nt++) {
                const int oc = nt * 8 + l4 * 2;
                float s0 = sS[oc], s1 = sS[oc + 1];
                float t0 = sT[oc], t1 = sT[oc + 1];
                float v0 = fmaxf(fmaf(d[mt][nt][0], s0, t0), 0.f);
                float v1 = fmaxf(fmaf(d[mt][nt][1], s1, t1), 0.f);
                float v2 = fmaxf(fmaf(d[mt][nt][2], s0, t0), 0.f);
                float v3 = fmaxf(fmaf(d[mt][nt][3], s1, t1), 0.f);
                float m0 = fmaxf(v0, v2);
                float m1 = fmaxf(v1, v3);
                m0 = fmaxf(m0, __shfl_xor_sync(0xffffffffu, m0, 4));
                m1 = fmaxf(m1, __shfl_xor_sync(0xffffffffu, m1, 4));
                if (valid) {
                    uint32_t idx = obase * 32 + nt * 4 + l4;
                    outh[idx] = pack_hi2(m0, m1);
                    outl[idx] = pack_lo2(m0, m1);
                }
            }
        }
        __syncthreads();
    }
}

// ---------------- tensor conv (layers 2-4): pair-in, copy staging ----------------
#define SMW   0            // weight frags: 147456 B
#define SMAH  147456       // activation hi: 180 cells * 36 words * 4 = 25920 B
#define SMAL  173376       // activation lo: 25920 B
#define SMC   199296       // BN consts: 512 B
#define CONV_SMEM 199808

__global__ void __launch_bounds__(128, 1)
conv_tensor(const uint4* __restrict__ inh, const uint4* __restrict__ inl,
            const uint4* __restrict__ wfrag,
            const float* __restrict__ cb, const float* __restrict__ gm,
            const float* __restrict__ bt, const float* __restrict__ mn,
            const float* __restrict__ vr,
            uint32_t* __restrict__ outh, uint32_t* __restrict__ outl,
            float* __restrict__ outf32,
            int H, int PH, int TR, int TC, int ntiles)
{
    extern __shared__ __align__(16) char smem[];
    const int tid = threadIdx.x;
    const int wrp = tid >> 5;
    const int lane = tid & 31;
    const int g = lane >> 2, l4 = lane & 3;

    {
        uint4* dw = (uint4*)(smem + SMW);
        for (int i = tid; i < 9216; i += 128) dw[i] = wfrag[i];
    }
    if (tid < 64) {
        float s = gm[tid] * rsqrtf(vr[tid] + 1e-3f);
        float t = (cb[tid] - mn[tid]) * s + bt[tid];
        ((float*)(smem + SMC))[tid] = s;
        ((float*)(smem + SMC + 256))[tid] = t;
    }
    __syncthreads();

    uint32_t* sAh = (uint32_t*)(smem + SMAH);
    uint32_t* sAl = (uint32_t*)(smem + SMAL);
    const uint4* sW = (const uint4*)(smem + SMW);
    const float* sS = (const float*)(smem + SMC);
    const float* sT = (const float*)(smem + SMC + 256);
    const int tpi = TR * TC;

    for (int tile = blockIdx.x; tile < ntiles; tile += gridDim.x) {
        const int img  = tile / tpi;
        const int rem  = tile - img * tpi;
        const int r0   = (rem / TC) * 16;
        const int c0   = (rem % TC) * 8;

        // ---- stage 18x10 window of 32 pairs: PURE COPIES (LDG.128 -> STS.128) ----
        for (int e = tid; e < 180 * 8; e += 128) {
            int grp  = e & 7;                 // uint4 group of 4 pairs
            int cell = e >> 3;                // wr*10 + wc
            int wr = cell / 10, wc = cell - 10 * wr;
            int gr = r0 - 1 + wr, gc = c0 - 1 + wc;
            uint4 vh = make_uint4(0, 0, 0, 0);
            uint4 vl = make_uint4(0, 0, 0, 0);
            if (gr >= 0 && gr < H && gc >= 0 && gc < H) {
                uint32_t idx = ((uint32_t)(img * H + gr) * H + gc) * 8 + grp;
                vh = __ldg(inh + idx);
                vl = __ldg(inl + idx);
            }
            // cell*36 words (144B, 16-aligned) + grp*4 words (16B) -> STS.128 ok
            *(uint4*)(sAh + cell * 36 + grp * 4) = vh;
            *(uint4*)(sAl + cell * 36 + grp * 4) = vl;
        }
        __syncthreads();

        float d[2][8][4];
#pragma unroll
        for (int mt = 0; mt < 2; mt++)
#pragma unroll
            for (int nt = 0; nt < 8; nt++)
#pragma unroll
                for (int j = 0; j < 4; j++) d[mt][nt][j] = 0.f;

        for (int tap = 0; tap < 9; tap++) {
            const int ky = tap / 3, kx = tap - 3 * (tap / 3);
#pragma unroll
            for (int ks = 0; ks < 4; ks++) {
                uint32_t ah[2][4], al[2][4];
#pragma unroll
                for (int mt = 0; mt < 2; mt++) {
                    const int rb = 4 * wrp + 2 * mt;
                    const int cell0 = (rb + ky) * 10 + (g + kx);
                    const int cell1 = cell0 + 10;
                    const int p0 = ks * 8 + l4;
                    ah[mt][0] = sAh[cell0 * 36 + p0];
                    ah[mt][1] = sAh[cell1 * 36 + p0];
                    ah[mt][2] = sAh[cell0 * 36 + p0 + 4];
                    ah[mt][3] = sAh[cell1 * 36 + p0 + 4];
                    al[mt][0] = sAl[cell0 * 36 + p0];
                    al[mt][1] = sAl[cell1 * 36 + p0];
                    al[mt][2] = sAl[cell0 * 36 + p0 + 4];
                    al[mt][3] = sAl[cell1 * 36 + p0 + 4];
                }
                const uint4* wb = sW + ((tap * 4 + ks) * 8) * 32 + lane;
                uint4 b[8];
#pragma unroll
                for (int nt = 0; nt < 8; nt++) b[nt] = wb[nt * 32];
#pragma unroll
                for (int nt = 0; nt < 8; nt++) {
                    MMA_BF16(d[0][nt], ah[0], b[nt].x, b[nt].y);   // hi*hi
                    MMA_BF16(d[1][nt], ah[1], b[nt].x, b[nt].y);
                }
#pragma unroll
                for (int nt = 0; nt < 8; nt++) {
                    MMA_BF16(d[0][nt], al[0], b[nt].x, b[nt].y);   // lo*hi
                    MMA_BF16(d[1][nt], al[1], b[nt].x, b[nt].y);
                }
#pragma unroll
                for (int nt = 0; nt < 8; nt++) {
                    MMA_BF16(d[0][nt], ah[0], b[nt].z, b[nt].w);   // hi*lo
                    MMA_BF16(d[1][nt], ah[1], b[nt].z, b[nt].w);
                }
            }
        }

        // ---- BN + ReLU + 2x2 maxpool + store (pair or fp32) ----
#pragma unroll
        for (int mt = 0; mt < 2; mt++) {
            const int pr = (r0 >> 1) + 2 * wrp + mt;
            const int pc = (c0 >> 1) + (g >> 1);
            const bool valid = ((g & 1) == 0) && pr < PH && pc < PH;
            const uint32_t obase = ((uint32_t)img * PH + pr) * PH + pc;
#pragma unroll
            for (int nt = 0; nt < 8; nt++) {
                const int oc = nt * 8 + l4 * 2;
                float s0 = sS[oc], s1 = sS[oc + 1];
                float t0 = sT[oc], t1 = sT[oc + 1];
                float v0 = fmaxf(fmaf(d[mt][nt][0], s0, t0), 0.f);
                float v1 = fmaxf(fmaf(d[mt][nt][1], s1, t1), 0.f);
                float v2 = fmaxf(fmaf(d[mt][nt][2], s0, t0), 0.f);
                float v3 = fmaxf(fmaf(d[mt][nt][3], s1, t1), 0.f);
                float m0 = fmaxf(v0, v2);
                float m1 = fmaxf(v1, v3);
                m0 = fmaxf(m0, __shfl_xor_sync(0xffffffffu, m0, 4));
                m1 = fmaxf(m1, __shfl_xor_sync(0xffffffffu, m1, 4));
                if (valid) {
                    if (outf32) {
                        *(float2*)(outf32 + (size_t)obase * 64 + oc) = make_float2(m0, m1);
                    } else {
                        uint32_t idx = obase * 32 + nt * 4 + l4;
                        outh[idx] = pack_hi2(m0, m1);
                        outl[idx] = pack_lo2(m0, m1);
                    }
                }
            }
        }
        __syncthreads();
    }
}

// ---------------- x @ Wk + bias ----------------
__global__ void xwk_gemm(const float* __restrict__ emb,
                         const float* __restrict__ Wk,
                         const float* __restrict__ bias,
                         float* __restrict__ outp)
{
    int idx = blockIdx.x * blockDim.x + threadIdx.x;
    if (idx >= NIMG * GATES) return;
    int u = idx & (GATES - 1);
    int n = idx >> 7;
    const float* e = emb + (size_t)n * DEMB;
    float acc = __ldg(bias + u);
#pragma unroll 4
    for (int k = 0; k < DEMB; k += 4) {
        float4 ev = *reinterpret_cast<const float4*>(e + k);
        acc = fmaf(ev.x, __ldg(Wk + (size_t)(k + 0) * GATES + u), acc);
        acc = fmaf(ev.y, __ldg(Wk + (size_t)(k + 1) * GATES + u), acc);
        acc = fmaf(ev.z, __ldg(Wk + (size_t)(k + 2) * GATES + u), acc);
        acc = fmaf(ev.w, __ldg(Wk + (size_t)(k + 3) * GATES + u), acc);
    }
    outp[idx] = acc;
}

// ---------------- LSTM chains over the BATCH axis ----------------
__device__ __forceinline__ float sigm(float x) { return 1.f / (1.f + expf(-x)); }

__global__ void lstm_chains(const float* __restrict__ xwkf,
                            const float* __restrict__ xwkb,
                            const float* __restrict__ Wrf,
                            const float* __restrict__ Wrb,
                            float* __restrict__ sf, float* __restrict__ sb2,
                            float* __restrict__ qf, float* __restrict__ qb)
{
    __shared__ float wr[HL * GATES];
    __shared__ float h[HL], c[HL], z[GATES];

    const int u     = threadIdx.x;
    const int chain = blockIdx.x;
    const int dir   = blockIdx.y;

    const float* xwk = dir ? xwkb : xwkf;
    const float* Wr  = dir ? Wrb  : Wrf;
    float* outp = (chain < NS) ? (dir ? sb2 : sf) : (dir ? qb : qf);
    const int cpos = (chain < NS) ? chain : (chain - NS);

#pragma unroll
    for (int k = 0; k < HL; k++) wr[k * GATES + u] = Wr[k * GATES + u];
    if (u < HL) { h[u] = 0.f; c[u] = 0.f; }
    __syncthreads();

    for (int t = 0; t < NB; t++) {
        const int b = dir ? (NB - 1 - t) : t;
        const int row = (chain < NS) ? (b * NS + cpos) : (400 + b * NQ + cpos);
        float acc = __ldg(xwk + (size_t)row * GATES + u);
#pragma unroll
        for (int k = 0; k < HL; k++) acc = fmaf(h[k], wr[k * GATES + u], acc);
        z[u] = acc;
        __syncthreads();
        if (u < HL) {
            float zi = z[u], zf = z[HL + u], zg = z[2 * HL + u], zo = z[3 * HL + u];
            float cc = sigm(zf) * c[u] + sigm(zi) * tanhf(zg);
            float hh = sigm(zo) * tanhf(cc);
            c[u] = cc; h[u] = hh;
            outp[(cpos * NB + b) * HL + u] = hh;
        }
        __syncthreads();
    }
}

// ---------------- attention readout + CE + accuracy ----------------
__global__ void readout(const float* __restrict__ sf, const float* __restrict__ sb2,
                        const float* __restrict__ qf, const float* __restrict__ qb,
                        const int* __restrict__ ysup, const int* __restrict__ yqry,
                        float* __restrict__ out)
{
    __shared__ float ce_sm[NQ * NB];
    __shared__ float corr_sm[NQ * NB];
    const int t = threadIdx.x;

    if (t < NQ * NB) {
        const int q = t / NB, b = t % NB;
        float vf[HL], vb[HL];
#pragma unroll
        for (int j = 0; j < HL; j++) {
            vf[j] = qf[(q * NB + b) * HL + j];
            vb[j] = qb[(q * NB + b) * HL + j];
        }
        float scores[NS];
        float mx = -1e30f;
        for (int s = 0; s < NS; s++) {
            float dot = 0.f, nrm = 0.f;
#pragma unroll
            for (int j = 0; j < HL; j++) {
                float a = sf[(s * NB + b) * HL + j];
                dot = fmaf(vf[j], a, dot); nrm = fmaf(a, a, nrm);
            }
#pragma unroll
            for (int j = 0; j < HL; j++) {
                float a = sb2[(s * NB + b) * HL + j];
                dot = fmaf(vb[j], a, dot); nrm = fmaf(a, a, nrm);
            }
            float sc = dot * rsqrtf(fmaxf(nrm, 1e-10f));
            scores[s] = sc; mx = fmaxf(mx, sc);
        }
        float sum = 0.f;
        for (int s = 0; s < NS; s++) { scores[s] = expf(scores[s] - mx); sum += scores[s]; }
        float inv = 1.f / sum;
        float preds[NWAY] = {0.f, 0.f, 0.f, 0.f, 0.f};
        for (int s = 0; s < NS; s++) preds[ysup[b * NS + s]] += scores[s] * inv;

        float psum = 0.f;
        for (int w = 0; w < NWAY; w++) psum += preds[w];
        const int yq = yqry[b * NQ + q];
        float pv = preds[yq] / psum;
        pv = fminf(fmaxf(pv, 1e-7f), 1.f - 1e-7f);
        ce_sm[t] = -logf(pv);

        int am = 0; float bv = preds[0];
        for (int w = 1; w < NWAY; w++) if (preds[w] > bv) { bv = preds[w]; am = w; }
        corr_sm[t] = (am == yq) ? 1.f : 0.f;
    }
    __syncthreads();
    if (t < NB) {
        float s = 0.f;
        for (int q = 0; q < NQ; q++) s += ce_sm[q * NB + t];
        out[t] = s / (float)NQ;
    }
    if (t == 16) {
        float s = 0.f;
        for (int i = 0; i < NQ * NB; i++) s += corr_sm[i];
        out[16] = s / (float)(NQ * NB);
    }
}

// ---------------- launch ----------------
extern "C" void kernel_launch(void* const* d_in, const int* in_sizes, int n_in,
                              void* d_out, int out_size)
{
    const float* xs = (const float*)d_in[0];
    const float* xq = (const float*)d_in[1];
    const int*   ys = (const int*)  d_in[2];
    const int*   yq = (const int*)  d_in[3];
    const float* w1 = (const float*)d_in[4];
    const float* w2 = (const float*)d_in[5];
    const float* w3 = (const float*)d_in[6];
    const float* w4 = (const float*)d_in[7];
    const float* cb = (const float*)d_in[8];
    const float* gm = (const float*)d_in[9];
    const float* bt = (const float*)d_in[10];
    const float* mn = (const float*)d_in[11];
    const float* vr = (const float*)d_in[12];
    const float* fk = (const float*)d_in[13];
    const float* fr = (const float*)d_in[14];
    const float* fb = (const float*)d_in[15];
    const float* bk = (const float*)d_in[16];
    const float* br = (const float*)d_in[17];
    const float* bb = (const float*)d_in[18];

    uint32_t *b1h, *b1l, *b2h, *b2l, *b3h, *b3l;
    float *emb, *xwkf, *xwkb, *sf, *sb, *qf, *qb;
    uint4 *wfrag, *wfrag1;
    cudaGetSymbolAddress((void**)&b1h, g_b1h);
    cudaGetSymbolAddress((void**)&b1l, g_b1l);
    cudaGetSymbolAddress((void**)&b2h, g_b2h);
    cudaGetSymbolAddress((void**)&b2l, g_b2l);
    cudaGetSymbolAddress((void**)&b3h, g_b3h);
    cudaGetSymbolAddress((void**)&b3l, g_b3l);
    cudaGetSymbolAddress((void**)&emb,  g_emb);
    cudaGetSymbolAddress((void**)&xwkf, g_xwkf);
    cudaGetSymbolAddress((void**)&xwkb, g_xwkb);
    cudaGetSymbolAddress((void**)&sf,   g_sf);
    cudaGetSymbolAddress((void**)&sb,   g_sb);
    cudaGetSymbolAddress((void**)&qf,   g_qf);
    cudaGetSymbolAddress((void**)&qb,   g_qb);
    cudaGetSymbolAddress((void**)&wfrag, g_wfrag);
    cudaGetSymbolAddress((void**)&wfrag1, g_wfrag1);

    cudaFuncSetAttribute(conv_tensor, cudaFuncAttributeMaxDynamicSharedMemorySize, CONV_SMEM);

    // weight fragment prep (tiny)
    prep_wfrag1<<<2, 256>>>(w1, wfrag1);
    prep_wfrag<<<36, 256>>>(w2, wfrag + 0 * 9216);
    prep_wfrag<<<36, 256>>>(w3, wfrag + 1 * 9216);
    prep_wfrag<<<36, 256>>>(w4, wfrag + 2 * 9216);

    // layer 1: tensor path, high-occupancy grid, pair output
    conv1_tensor<<<1184, 128>>>(xs, xq, wfrag1,
        cb + 0, gm + 0, bt + 0, mn + 0, vr + 0, b1h, b1l);

    // layers 2-4: mma.sync bf16 tensor path (persistent, grid=148), pair dataflow
    conv_tensor<<<148, 128, CONV_SMEM>>>(
        (const uint4*)b1h, (const uint4*)b1l, wfrag + 0 * 9216,
        cb + 64,  gm + 64,  bt + 64,  mn + 64,  vr + 64,
        b2h, b2l, nullptr, 42, 21, 3, 6, 640 * 18);
    conv_tensor<<<148, 128, CONV_SMEM>>>(
        (const uint4*)b2h, (const uint4*)b2l, wfrag + 1 * 9216,
        cb + 128, gm + 128, bt + 128, mn + 128, vr + 128,
        b3h, b3l, nullptr, 21, 10, 2, 3, 640 * 6);
    conv_tensor<<<148, 128, CONV_SMEM>>>(
        (const uint4*)b3h, (const uint4*)b3l, wfrag + 2 * 9216,
        cb + 192, gm + 192, bt + 192, mn + 192, vr + 192,
        nullptr, nullptr, emb, 10, 5, 1, 2, 640 * 2);

    // FCE input projections
    xwk_gemm<<<(NIMG * GATES + 255) / 256, 256>>>(emb, fk, fb, xwkf);
    xwk_gemm<<<(NIMG * GATES + 255) / 256, 256>>>(emb, bk, bb, xwkb);

    // FCE chains (recurrence over the batch axis)
    lstm_chains<<<dim3(40, 2), GATES>>>(xwkf, xwkb, fr, br, sf, sb, qf, qb);

    // attention + CE + acc
    readout<<<1, 256>>>(sf, sb, qf, qb, ys, yq, (float*)d_out);
}

// round 16
// speedup vs baseline: 1.2224x; 1.0705x over previous
#include <cuda_runtime.h>
#include <cuda_bf16.h>
#include <math.h>
#include <stdint.h>

// ---------------- problem constants ----------------
#define NB 16
#define NS 25
#define NQ 15
#define NWAY 5
#define NIMG 640            // 400 support + 240 query
#define HL 32
#define DEMB 1600           // 5*5*64
#define GATES 128           // 4*HL

// ---------------- scratch (device globals; no allocations allowed) ----------------
// activations between conv layers: bf16 pairs [img][H][W][32] uint32 (hi, lo)
__device__ uint32_t g_b1h[640 * 42 * 42 * 32];
__device__ uint32_t g_b1l[640 * 42 * 42 * 32];
__device__ uint32_t g_b2h[640 * 21 * 21 * 32];
__device__ uint32_t g_b2l[640 * 21 * 21 * 32];
__device__ uint32_t g_b3h[640 * 10 * 10 * 32];
__device__ uint32_t g_b3l[640 * 10 * 10 * 32];
__device__ float g_emb [640 * DEMB];           // embeddings (5*5*64) fp32
__device__ float g_xwkf[640 * GATES];
__device__ float g_xwkb[640 * GATES];
__device__ float g_sf[NS * NB * HL];
__device__ float g_sb[NS * NB * HL];
__device__ float g_qf[NQ * NB * HL];
__device__ float g_qb[NQ * NB * HL];

// weight fragments for mma.sync m16n8k16: layers 2-4: [tap][kstep][ntile][lane]
// uint4 = {bhi0, bhi1, blo0, blo1}  (9*4*8*32 = 9216 uint4 = 144KB per layer)
__device__ uint4 g_wfrag[3][9216];
// layer 1 fragments: [kstep(2)][ntile(8)][lane(32)] = 512 uint4 (K=27 padded to 32)
__device__ uint4 g_wfrag1[512];

// ---------------- bf16 split helpers ----------------
__device__ __forceinline__ uint32_t pack_hi2(float x0, float x1) {
    __nv_bfloat162 p = __halves2bfloat162(__float2bfloat16(x0), __float2bfloat16(x1));
    return *reinterpret_cast<uint32_t*>(&p);
}
__device__ __forceinline__ uint32_t pack_lo2(float x0, float x1) {
    __nv_bfloat16 h0 = __float2bfloat16(x0);
    __nv_bfloat16 h1 = __float2bfloat16(x1);
    __nv_bfloat162 p = __halves2bfloat162(__float2bfloat16(x0 - __bfloat162float(h0)),
                                          __float2bfloat16(x1 - __bfloat162float(h1)));
    return *reinterpret_cast<uint32_t*>(&p);
}

#define MMA_BF16(d, a, b0, b1) \
    asm volatile("mma.sync.aligned.m16n8k16.row.col.f32.bf16.bf16.f32 " \
        "{%0,%1,%2,%3}, {%4,%5,%6,%7}, {%8,%9}, {%0,%1,%2,%3};" \
        : "+f"((d)[0]), "+f"((d)[1]), "+f"((d)[2]), "+f"((d)[3]) \
        : "r"((a)[0]), "r"((a)[1]), "r"((a)[2]), "r"((a)[3]), "r"(b0), "r"(b1))

// ---------------- weight fragment prep (layers 2-4) ----------------
__global__ void prep_wfrag(const float* __restrict__ w, uint4* __restrict__ dst)
{
    int i = blockIdx.x * 256 + threadIdx.x;
    if (i >= 9216) return;
    int lane = i & 31;
    int nt   = (i >> 5) & 7;
    int ks   = (i >> 8) & 3;
    int tap  = i >> 10;
    int g = lane >> 2, l4 = lane & 3;
    int n  = nt * 8 + g;
    int k0 = ks * 16 + l4 * 2;
    float x00 = w[(tap * 64 + k0 + 0) * 64 + n];
    float x01 = w[(tap * 64 + k0 + 1) * 64 + n];
    float x10 = w[(tap * 64 + k0 + 8) * 64 + n];
    float x11 = w[(tap * 64 + k0 + 9) * 64 + n];
    uint4 o;
    o.x = pack_hi2(x00, x01);
    o.y = pack_hi2(x10, x11);
    o.z = pack_lo2(x00, x01);
    o.w = pack_lo2(x10, x11);
    dst[i] = o;
}

// ---------------- weight fragment prep (layer 1, K=27 padded to 32) ----------------
__global__ void prep_wfrag1(const float* __restrict__ w, uint4* __restrict__ dst)
{
    int i = blockIdx.x * 256 + threadIdx.x;
    if (i >= 512) return;
    int lane = i & 31;
    int nt   = (i >> 5) & 7;
    int ks   = i >> 8;
    int g = lane >> 2, l4 = lane & 3;
    int n  = nt * 8 + g;
    int k0 = ks * 16 + l4 * 2;
    float x[4];
#pragma unroll
    for (int j = 0; j < 4; j++) {
        int k = k0 + (j >> 1) * 8 + (j & 1);
        x[j] = (k < 27) ? w[k * 64 + n] : 0.f;   // flat [tap*3+cin][64]
    }
    uint4 o;
    o.x = pack_hi2(x[0], x[1]);
    o.y = pack_hi2(x[2], x[3]);
    o.z = pack_lo2(x[0], x[1]);
    o.w = pack_lo2(x[2], x[3]);
    dst[i] = o;
}

// ---------------- layer 1: tensor conv via padded im2col (pair out) ------------
__global__ void __launch_bounds__(128)
conv1_tensor(const float* __restrict__ in_sup,
             const float* __restrict__ in_qry,
             const uint4* __restrict__ wfrag1,
             const float* __restrict__ cb, const float* __restrict__ gm,
             const float* __restrict__ bt, const float* __restrict__ mn,
             const float* __restrict__ vr,
             uint32_t* __restrict__ outh, uint32_t* __restrict__ outl)
{
    __shared__ float sWin[540];          // 18 x 10 x 3 fp32 window
    __shared__ uint4 sB[512];
    __shared__ float sS[64], sT[64];

    const int tid = threadIdx.x;
    const int wrp = tid >> 5;
    const int lane = tid & 31;
    const int g = lane >> 2, l4 = lane & 3;

    for (int i = tid; i < 512; i += 128) sB[i] = __ldg(wfrag1 + i);
    if (tid < 64) {
        float s = gm[tid] * rsqrtf(vr[tid] + 1e-3f);
        sS[tid] = s;
        sT[tid] = (cb[tid] - mn[tid]) * s + bt[tid];
    }
    __syncthreads();

    const int TR = 6, TC = 11, tpi = TR * TC;
    const int ntiles = NIMG * tpi;

    for (int tile = blockIdx.x; tile < ntiles; tile += gridDim.x) {
        const int img = tile / tpi;
        const int rem = tile - img * tpi;
        const int r0  = (rem / TC) * 16;
        const int c0  = (rem % TC) * 8;
        const float* base = (img < 400) ? (in_sup + (size_t)img * 84 * 84 * 3)
                                        : (in_qry + (size_t)(img - 400) * 84 * 84 * 3);

        for (int e = tid; e < 540; e += 128) {
            int cell = e / 3, ch = e - 3 * cell;
            int wr = cell / 10, wc = cell - 10 * wr;
            int gr = r0 - 1 + wr, gc = c0 - 1 + wc;
            float v = 0.f;
            if (gr >= 0 && gr < 84 && gc >= 0 && gc < 84)
                v = __ldg(base + ((size_t)gr * 84 + gc) * 3 + ch);
            sWin[e] = v;
        }
        __syncthreads();

        float d[2][8][4];
#pragma unroll
        for (int mt = 0; mt < 2; mt++)
#pragma unroll
            for (int nt = 0; nt < 8; nt++)
#pragma unroll
                for (int j = 0; j < 4; j++) d[mt][nt][j] = 0.f;

        auto l1v = [&](int prow, int k) -> float {
            if (k >= 27) return 0.f;
            int tap = k / 3, ch = k - 3 * tap;
            int ky = tap / 3, kx = tap - 3 * ky;
            return sWin[((prow + ky) * 10 + (g + kx)) * 3 + ch];
        };

#pragma unroll
        for (int ks = 0; ks < 2; ks++) {
            uint32_t ah[2][4], al[2][4];
#pragma unroll
            for (int mt = 0; mt < 2; mt++) {
                const int rb = 4 * wrp + 2 * mt;
                const int k0 = ks * 16 + 2 * l4;
                float x00 = l1v(rb,     k0),     x01 = l1v(rb,     k0 + 1);
                float x10 = l1v(rb + 1, k0),     x11 = l1v(rb + 1, k0 + 1);
                float x20 = l1v(rb,     k0 + 8), x21 = l1v(rb,     k0 + 9);
                float x30 = l1v(rb + 1, k0 + 8), x31 = l1v(rb + 1, k0 + 9);
                ah[mt][0] = pack_hi2(x00, x01); al[mt][0] = pack_lo2(x00, x01);
                ah[mt][1] = pack_hi2(x10, x11); al[mt][1] = pack_lo2(x10, x11);
                ah[mt][2] = pack_hi2(x20, x21); al[mt][2] = pack_lo2(x20, x21);
                ah[mt][3] = pack_hi2(x30, x31); al[mt][3] = pack_lo2(x30, x31);
            }
            uint4 b[8];
#pragma unroll
            for (int nt = 0; nt < 8; nt++) b[nt] = sB[(ks * 8 + nt) * 32 + lane];
#pragma unroll
            for (int nt = 0; nt < 8; nt++) {
                MMA_BF16(d[0][nt], ah[0], b[nt].x, b[nt].y);
                MMA_BF16(d[1][nt], ah[1], b[nt].x, b[nt].y);
            }
#pragma unroll
            for (int nt = 0; nt < 8; nt++) {
                MMA_BF16(d[0][nt], al[0], b[nt].x, b[nt].y);
                MMA_BF16(d[1][nt], al[1], b[nt].x, b[nt].y);
            }
#pragma unroll
            for (int nt = 0; nt < 8; nt++) {
                MMA_BF16(d[0][nt], ah[0], b[nt].z, b[nt].w);
                MMA_BF16(d[1][nt], ah[1], b[nt].z, b[nt].w);
            }
        }

        // BN + ReLU + 2x2 pool + pair store
#pragma unroll
        for (int mt = 0; mt < 2; mt++) {
            const int pr = (r0 >> 1) + 2 * wrp + mt;
            const int pc = (c0 >> 1) + (g >> 1);
            const bool valid = ((g & 1) == 0) && pr < 42 && pc < 42;
            const uint32_t obase = ((uint32_t)img * 42 + pr) * 42 + pc;
#pragma unroll
            for (int nt = 0; nt < 8; nt++) {
                const int oc = nt * 8 + l4 * 2;
                float s0 = sS[oc], s1 = sS[oc + 1];
                float t0 = sT[oc], t1 = sT[oc + 1];
                float v0 = fmaxf(fmaf(d[mt][nt][0], s0, t0), 0.f);
                float v1 = fmaxf(fmaf(d[mt][nt][1], s1, t1), 0.f);
                float v2 = fmaxf(fmaf(d[mt][nt][2], s0, t0), 0.f);
                float v3 = fmaxf(fmaf(d[mt][nt][3], s1, t1), 0.f);
                float m0 = fmaxf(v0, v2);
                float m1 = fmaxf(v1, v3);
                m0 = fmaxf(m0, __shfl_xor_sync(0xffffffffu, m0, 4));
                m1 = fmaxf(m1, __shfl_xor_sync(0xffffffffu, m1, 4));
                if (valid) {
                    uint32_t idx = obase * 32 + nt * 4 + l4;
                    outh[idx] = pack_hi2(m0, m1);
                    outl[idx] = pack_lo2(m0, m1);
                }
            }
        }
        __syncthreads();
    }
}

// ---------------- tensor conv (layers 2-4): B frags via L1, small smem ----------
// SMEM = A staging only (52KB) -> 3-4 CTAs/SM; B fragments read through __ldg
// (144KB table, L1-resident per SM).
#define SMAH2  0                         // activation hi: 180*36*4 = 25920 B
#define SMAL2  25920                     // activation lo: 25920 B
#define SMC2   51840                     // BN consts: 512 B
#define CONV2_SMEM 52352

__global__ void __launch_bounds__(128)
conv_tensor(const uint4* __restrict__ inh, const uint4* __restrict__ inl,
            const uint4* __restrict__ wfrag,
            const float* __restrict__ cb, const float* __restrict__ gm,
            const float* __restrict__ bt, const float* __restrict__ mn,
            const float* __restrict__ vr,
            uint32_t* __restrict__ outh, uint32_t* __restrict__ outl,
            float* __restrict__ outf32,
            int H, int PH, int TR, int TC, int ntiles)
{
    extern __shared__ __align__(16) char smem[];
    const int tid = threadIdx.x;
    const int wrp = tid >> 5;
    const int lane = tid & 31;
    const int g = lane >> 2, l4 = lane & 3;

    if (tid < 64) {
        float s = gm[tid] * rsqrtf(vr[tid] + 1e-3f);
        float t = (cb[tid] - mn[tid]) * s + bt[tid];
        ((float*)(smem + SMC2))[tid] = s;
        ((float*)(smem + SMC2 + 256))[tid] = t;
    }
    __syncthreads();

    uint32_t* sAh = (uint32_t*)(smem + SMAH2);
    uint32_t* sAl = (uint32_t*)(smem + SMAL2);
    const float* sS = (const float*)(smem + SMC2);
    const float* sT = (const float*)(smem + SMC2 + 256);
    const int tpi = TR * TC;

    for (int tile = blockIdx.x; tile < ntiles; tile += gridDim.x) {
        const int img  = tile / tpi;
        const int rem  = tile - img * tpi;
        const int r0   = (rem / TC) * 16;
        const int c0   = (rem % TC) * 8;

        // ---- stage 18x10 window of 32 pairs: pure copies (LDG.128 -> STS.128) ----
        for (int e = tid; e < 180 * 8; e += 128) {
            int grp  = e & 7;
            int cell = e >> 3;
            int wr = cell / 10, wc = cell - 10 * wr;
            int gr = r0 - 1 + wr, gc = c0 - 1 + wc;
            uint4 vh = make_uint4(0, 0, 0, 0);
            uint4 vl = make_uint4(0, 0, 0, 0);
            if (gr >= 0 && gr < H && gc >= 0 && gc < H) {
                uint32_t idx = ((uint32_t)(img * H + gr) * H + gc) * 8 + grp;
                vh = __ldg(inh + idx);
                vl = __ldg(inl + idx);
            }
            *(uint4*)(sAh + cell * 36 + grp * 4) = vh;
            *(uint4*)(sAl + cell * 36 + grp * 4) = vl;
        }
        __syncthreads();

        float d[2][8][4];
#pragma unroll
        for (int mt = 0; mt < 2; mt++)
#pragma unroll
            for (int nt = 0; nt < 8; nt++)
#pragma unroll
                for (int j = 0; j < 4; j++) d[mt][nt][j] = 0.f;

        for (int tap = 0; tap < 9; tap++) {
            const int ky = tap / 3, kx = tap - 3 * (tap / 3);
#pragma unroll
            for (int ks = 0; ks < 4; ks++) {
                uint32_t ah[2][4], al[2][4];
#pragma unroll
                for (int mt = 0; mt < 2; mt++) {
                    const int rb = 4 * wrp + 2 * mt;
                    const int cell0 = (rb + ky) * 10 + (g + kx);
                    const int cell1 = cell0 + 10;
                    const int p0 = ks * 8 + l4;
                    ah[mt][0] = sAh[cell0 * 36 + p0];
                    ah[mt][1] = sAh[cell1 * 36 + p0];
                    ah[mt][2] = sAh[cell0 * 36 + p0 + 4];
                    ah[mt][3] = sAh[cell1 * 36 + p0 + 4];
                    al[mt][0] = sAl[cell0 * 36 + p0];
                    al[mt][1] = sAl[cell1 * 36 + p0];
                    al[mt][2] = sAl[cell0 * 36 + p0 + 4];
                    al[mt][3] = sAl[cell1 * 36 + p0 + 4];
                }
                // B fragments via read-only global loads (L1-resident table)
                const uint4* wb = wfrag + ((tap * 4 + ks) * 8) * 32 + lane;
                uint4 b[8];
#pragma unroll
                for (int nt = 0; nt < 8; nt++) b[nt] = __ldg(wb + nt * 32);
#pragma unroll
                for (int nt = 0; nt < 8; nt++) {
                    MMA_BF16(d[0][nt], ah[0], b[nt].x, b[nt].y);   // hi*hi
                    MMA_BF16(d[1][nt], ah[1], b[nt].x, b[nt].y);
                }
#pragma unroll
                for (int nt = 0; nt < 8; nt++) {
                    MMA_BF16(d[0][nt], al[0], b[nt].x, b[nt].y);   // lo*hi
                    MMA_BF16(d[1][nt], al[1], b[nt].x, b[nt].y);
                }
#pragma unroll
                for (int nt = 0; nt < 8; nt++) {
                    MMA_BF16(d[0][nt], ah[0], b[nt].z, b[nt].w);   // hi*lo
                    MMA_BF16(d[1][nt], ah[1], b[nt].z, b[nt].w);
                }
            }
        }

        // ---- BN + ReLU + 2x2 maxpool + store (pair or fp32) ----
#pragma unroll
        for (int mt = 0; mt < 2; mt++) {
            const int pr = (r0 >> 1) + 2 * wrp + mt;
            const int pc = (c0 >> 1) + (g >> 1);
            const bool valid = ((g & 1) == 0) && pr < PH && pc < PH;
            const uint32_t obase = ((uint32_t)img * PH + pr) * PH + pc;
#pragma unroll
            for (int nt = 0; nt < 8; nt++) {
                const int oc = nt * 8 + l4 * 2;
                float s0 = sS[oc], s1 = sS[oc + 1];
                float t0 = sT[oc], t1 = sT[oc + 1];
                float v0 = fmaxf(fmaf(d[mt][nt][0], s0, t0), 0.f);
                float v1 = fmaxf(fmaf(d[mt][nt][1], s1, t1), 0.f);
                float v2 = fmaxf(fmaf(d[mt][nt][2], s0, t0), 0.f);
                float v3 = fmaxf(fmaf(d[mt][nt][3], s1, t1), 0.f);
                float m0 = fmaxf(v0, v2);
                float m1 = fmaxf(v1, v3);
                m0 = fmaxf(m0, __shfl_xor_sync(0xffffffffu, m0, 4));
                m1 = fmaxf(m1, __shfl_xor_sync(0xffffffffu, m1, 4));
                if (valid) {
                    if (outf32) {
                        *(float2*)(outf32 + (size_t)obase * 64 + oc) = make_float2(m0, m1);
                    } else {
                        uint32_t idx = obase * 32 + nt * 4 + l4;
                        outh[idx] = pack_hi2(m0, m1);
                        outl[idx] = pack_lo2(m0, m1);
                    }
                }
            }
        }
        __syncthreads();
    }
}

// ---------------- x @ Wk + bias ----------------
__global__ void xwk_gemm(const float* __restrict__ emb,
                         const float* __restrict__ Wk,
                         const float* __restrict__ bias,
                         float* __restrict__ outp)
{
    int idx = blockIdx.x * blockDim.x + threadIdx.x;
    if (idx >= NIMG * GATES) return;
    int u = idx & (GATES - 1);
    int n = idx >> 7;
    const float* e = emb + (size_t)n * DEMB;
    float acc = __ldg(bias + u);
#pragma unroll 4
    for (int k = 0; k < DEMB; k += 4) {
        float4 ev = *reinterpret_cast<const float4*>(e + k);
        acc = fmaf(ev.x, __ldg(Wk + (size_t)(k + 0) * GATES + u), acc);
        acc = fmaf(ev.y, __ldg(Wk + (size_t)(k + 1) * GATES + u), acc);
        acc = fmaf(ev.z, __ldg(Wk + (size_t)(k + 2) * GATES + u), acc);
        acc = fmaf(ev.w, __ldg(Wk + (size_t)(k + 3) * GATES + u), acc);
    }
    outp[idx] = acc;
}

// ---------------- LSTM chains over the BATCH axis ----------------
__device__ __forceinline__ float sigm(float x) { return 1.f / (1.f + expf(-x)); }

__global__ void lstm_chains(const float* __restrict__ xwkf,
                            const float* __restrict__ xwkb,
                            const float* __restrict__ Wrf,
                            const float* __restrict__ Wrb,
                            float* __restrict__ sf, float* __restrict__ sb2,
                            float* __restrict__ qf, float* __restrict__ qb)
{
    __shared__ float wr[HL * GATES];
    __shared__ float h[HL], c[HL], z[GATES];

    const int u     = threadIdx.x;
    const int chain = blockIdx.x;
    const int dir   = blockIdx.y;

    const float* xwk = dir ? xwkb : xwkf;
    const float* Wr  = dir ? Wrb  : Wrf;
    float* outp = (chain < NS) ? (dir ? sb2 : sf) : (dir ? qb : qf);
    const int cpos = (chain < NS) ? chain : (chain - NS);

#pragma unroll
    for (int k = 0; k < HL; k++) wr[k * GATES + u] = Wr[k * GATES + u];
    if (u < HL) { h[u] = 0.f; c[u] = 0.f; }
    __syncthreads();

    for (int t = 0; t < NB; t++) {
        const int b = dir ? (NB - 1 - t) : t;
        const int row = (chain < NS) ? (b * NS + cpos) : (400 + b * NQ + cpos);
        float acc = __ldg(xwk + (size_t)row * GATES + u);
#pragma unroll
        for (int k = 0; k < HL; k++) acc = fmaf(h[k], wr[k * GATES + u], acc);
        z[u] = acc;
        __syncthreads();
        if (u < HL) {
            float zi = z[u], zf = z[HL + u], zg = z[2 * HL + u], zo = z[3 * HL + u];
            float cc = sigm(zf) * c[u] + sigm(zi) * tanhf(zg);
            float hh = sigm(zo) * tanhf(cc);
            c[u] = cc; h[u] = hh;
            outp[(cpos * NB + b) * HL + u] = hh;
        }
        __syncthreads();
    }
}

// ---------------- attention readout + CE + accuracy ----------------
__global__ void readout(const float* __restrict__ sf, const float* __restrict__ sb2,
                        const float* __restrict__ qf, const float* __restrict__ qb,
                        const int* __restrict__ ysup, const int* __restrict__ yqry,
                        float* __restrict__ out)
{
    __shared__ float ce_sm[NQ * NB];
    __shared__ float corr_sm[NQ * NB];
    const int t = threadIdx.x;

    if (t < NQ * NB) {
        const int q = t / NB, b = t % NB;
        float vf[HL], vb[HL];
#pragma unroll
        for (int j = 0; j < HL; j++) {
            vf[j] = qf[(q * NB + b) * HL + j];
            vb[j] = qb[(q * NB + b) * HL + j];
        }
        float scores[NS];
        float mx = -1e30f;
        for (int s = 0; s < NS; s++) {
            float dot = 0.f, nrm = 0.f;
#pragma unroll
            for (int j = 0; j < HL; j++) {
                float a = sf[(s * NB + b) * HL + j];
                dot = fmaf(vf[j], a, dot); nrm = fmaf(a, a, nrm);
            }
#pragma unroll
            for (int j = 0; j < HL; j++) {
                float a = sb2[(s * NB + b) * HL + j];
                dot = fmaf(vb[j], a, dot); nrm = fmaf(a, a, nrm);
            }
            float sc = dot * rsqrtf(fmaxf(nrm, 1e-10f));
            scores[s] = sc; mx = fmaxf(mx, sc);
        }
        float sum = 0.f;
        for (int s = 0; s < NS; s++) { scores[s] = expf(scores[s] - mx); sum += scores[s]; }
        float inv = 1.f / sum;
        float preds[NWAY] = {0.f, 0.f, 0.f, 0.f, 0.f};
        for (int s = 0; s < NS; s++) preds[ysup[b * NS + s]] += scores[s] * inv;

        float psum = 0.f;
        for (int w = 0; w < NWAY; w++) psum += preds[w];
        const int yq = yqry[b * NQ + q];
        float pv = preds[yq] / psum;
        pv = fminf(fmaxf(pv, 1e-7f), 1.f - 1e-7f);
        ce_sm[t] = -logf(pv);

        int am = 0; float bv = preds[0];
        for (int w = 1; w < NWAY; w++) if (preds[w] > bv) { bv = preds[w]; am = w; }
        corr_sm[t] = (am == yq) ? 1.f : 0.f;
    }
    __syncthreads();
    if (t < NB) {
        float s = 0.f;
        for (int q = 0; q < NQ; q++) s += ce_sm[q * NB + t];
        out[t] = s / (float)NQ;
    }
    if (t == 16) {
        float s = 0.f;
        for (int i = 0; i < NQ * NB; i++) s += corr_sm[i];
        out[16] = s / (float)(NQ * NB);
    }
}

// ---------------- launch ----------------
extern "C" void kernel_launch(void* const* d_in, const int* in_sizes, int n_in,
                              void* d_out, int out_size)
{
    const float* xs = (const float*)d_in[0];
    const float* xq = (const float*)d_in[1];
    const int*   ys = (const int*)  d_in[2];
    const int*   yq = (const int*)  d_in[3];
    const float* w1 = (const float*)d_in[4];
    const float* w2 = (const float*)d_in[5];
    const float* w3 = (const float*)d_in[6];
    const float* w4 = (const float*)d_in[7];
    const float* cb = (const float*)d_in[8];
    const float* gm = (const float*)d_in[9];
    const float* bt = (const float*)d_in[10];
    const float* mn = (const float*)d_in[11];
    const float* vr = (const float*)d_in[12];
    const float* fk = (const float*)d_in[13];
    const float* fr = (const float*)d_in[14];
    const float* fb = (const float*)d_in[15];
    const float* bk = (const float*)d_in[16];
    const float* br = (const float*)d_in[17];
    const float* bb = (const float*)d_in[18];

    uint32_t *b1h, *b1l, *b2h, *b2l, *b3h, *b3l;
    float *emb, *xwkf, *xwkb, *sf, *sb, *qf, *qb;
    uint4 *wfrag, *wfrag1;
    cudaGetSymbolAddress((void**)&b1h, g_b1h);
    cudaGetSymbolAddress((void**)&b1l, g_b1l);
    cudaGetSymbolAddress((void**)&b2h, g_b2h);
    cudaGetSymbolAddress((void**)&b2l, g_b2l);
    cudaGetSymbolAddress((void**)&b3h, g_b3h);
    cudaGetSymbolAddress((void**)&b3l, g_b3l);
    cudaGetSymbolAddress((void**)&emb,  g_emb);
    cudaGetSymbolAddress((void**)&xwkf, g_xwkf);
    cudaGetSymbolAddress((void**)&xwkb, g_xwkb);
    cudaGetSymbolAddress((void**)&sf,   g_sf);
    cudaGetSymbolAddress((void**)&sb,   g_sb);
    cudaGetSymbolAddress((void**)&qf,   g_qf);
    cudaGetSymbolAddress((void**)&qb,   g_qb);
    cudaGetSymbolAddress((void**)&wfrag, g_wfrag);
    cudaGetSymbolAddress((void**)&wfrag1, g_wfrag1);

    cudaFuncSetAttribute(conv_tensor, cudaFuncAttributeMaxDynamicSharedMemorySize, CONV2_SMEM);

    // weight fragment prep (tiny)
    prep_wfrag1<<<2, 256>>>(w1, wfrag1);
    prep_wfrag<<<36, 256>>>(w2, wfrag + 0 * 9216);
    prep_wfrag<<<36, 256>>>(w3, wfrag + 1 * 9216);
    prep_wfrag<<<36, 256>>>(w4, wfrag + 2 * 9216);

    // layer 1: tensor path, high-occupancy grid, pair output
    conv1_tensor<<<1184, 128>>>(xs, xq, wfrag1,
        cb + 0, gm + 0, bt + 0, mn + 0, vr + 0, b1h, b1l);

    // layers 2-4: mma.sync bf16 tensor path; B via L1, small smem, 3-4 CTAs/SM
    conv_tensor<<<592, 128, CONV2_SMEM>>>(
        (const uint4*)b1h, (const uint4*)b1l, wfrag + 0 * 9216,
        cb + 64,  gm + 64,  bt + 64,  mn + 64,  vr + 64,
        b2h, b2l, nullptr, 42, 21, 3, 6, 640 * 18);
    conv_tensor<<<592, 128, CONV2_SMEM>>>(
        (const uint4*)b2h, (const uint4*)b2l, wfrag + 1 * 9216,
        cb + 128, gm + 128, bt + 128, mn + 128, vr + 128,
        b3h, b3l, nullptr, 21, 10, 2, 3, 640 * 6);
    conv_tensor<<<592, 128, CONV2_SMEM>>>(
        (const uint4*)b3h, (const uint4*)b3l, wfrag + 2 * 9216,
        cb + 192, gm + 192, bt + 192, mn + 192, vr + 192,
        nullptr, nullptr, emb, 10, 5, 1, 2, 640 * 2);

    // FCE input projections
    xwk_gemm<<<(NIMG * GATES + 255) / 256, 256>>>(emb, fk, fb, xwkf);
    xwk_gemm<<<(NIMG * GATES + 255) / 256, 256>>>(emb, bk, bb, xwkb);

    // FCE chains (recurrence over the batch axis)
    lstm_chains<<<dim3(40, 2), GATES>>>(xwkf, xwkb, fr, br, sf, sb, qf, qb);

    // attention + CE + acc
    readout<<<1, 256>>>(sf, sb, qf, qb, ys, yq, (float*)d_out);
}

// round 17
// speedup vs baseline: 1.2881x; 1.0537x over previous
#include <cuda_runtime.h>
#include <cuda_bf16.h>
#include <math.h>
#include <stdint.h>

// ---------------- problem constants ----------------
#define NB 16
#define NS 25
#define NQ 15
#define NWAY 5
#define NIMG 640            // 400 support + 240 query
#define HL 32
#define DEMB 1600           // 5*5*64
#define GATES 128           // 4*HL

// ---------------- scratch (device globals; no allocations allowed) ----------------
__device__ uint32_t g_b1h[640 * 42 * 42 * 32];
__device__ uint32_t g_b1l[640 * 42 * 42 * 32];
__device__ uint32_t g_b2h[640 * 21 * 21 * 32];
__device__ uint32_t g_b2l[640 * 21 * 21 * 32];
__device__ uint32_t g_b3h[640 * 10 * 10 * 32];
__device__ uint32_t g_b3l[640 * 10 * 10 * 32];
__device__ float g_emb [640 * DEMB];
__device__ float g_xwkf[640 * GATES];
__device__ float g_xwkb[640 * GATES];
__device__ float g_sf[NS * NB * HL];
__device__ float g_sb[NS * NB * HL];
__device__ float g_qf[NQ * NB * HL];
__device__ float g_qb[NQ * NB * HL];

__device__ uint4 g_wfrag[3][9216];
__device__ uint4 g_wfrag1[512];

// ---------------- bf16 split helpers ----------------
__device__ __forceinline__ uint32_t pack_hi2(float x0, float x1) {
    __nv_bfloat162 p = __halves2bfloat162(__float2bfloat16(x0), __float2bfloat16(x1));
    return *reinterpret_cast<uint32_t*>(&p);
}
__device__ __forceinline__ uint32_t pack_lo2(float x0, float x1) {
    __nv_bfloat16 h0 = __float2bfloat16(x0);
    __nv_bfloat16 h1 = __float2bfloat16(x1);
    __nv_bfloat162 p = __halves2bfloat162(__float2bfloat16(x0 - __bfloat162float(h0)),
                                          __float2bfloat16(x1 - __bfloat162float(h1)));
    return *reinterpret_cast<uint32_t*>(&p);
}

#define MMA_BF16(d, a, b0, b1) \
    asm volatile("mma.sync.aligned.m16n8k16.row.col.f32.bf16.bf16.f32 " \
        "{%0,%1,%2,%3}, {%4,%5,%6,%7}, {%8,%9}, {%0,%1,%2,%3};" \
        : "+f"((d)[0]), "+f"((d)[1]), "+f"((d)[2]), "+f"((d)[3]) \
        : "r"((a)[0]), "r"((a)[1]), "r"((a)[2]), "r"((a)[3]), "r"(b0), "r"(b1))

#define LDSM4(r, addr) \
    asm volatile("ldmatrix.sync.aligned.m8n8.x4.shared.b16 {%0,%1,%2,%3}, [%4];" \
        : "=r"((r)[0]), "=r"((r)[1]), "=r"((r)[2]), "=r"((r)[3]) : "r"(addr))

// ---------------- weight fragment prep (layers 2-4) ----------------
__global__ void prep_wfrag(const float* __restrict__ w, uint4* __restrict__ dst)
{
    int i = blockIdx.x * 256 + threadIdx.x;
    if (i >= 9216) return;
    int lane = i & 31;
    int nt   = (i >> 5) & 7;
    int ks   = (i >> 8) & 3;
    int tap  = i >> 10;
    int g = lane >> 2, l4 = lane & 3;
    int n  = nt * 8 + g;
    int k0 = ks * 16 + l4 * 2;
    float x00 = w[(tap * 64 + k0 + 0) * 64 + n];
    float x01 = w[(tap * 64 + k0 + 1) * 64 + n];
    float x10 = w[(tap * 64 + k0 + 8) * 64 + n];
    float x11 = w[(tap * 64 + k0 + 9) * 64 + n];
    uint4 o;
    o.x = pack_hi2(x00, x01);
    o.y = pack_hi2(x10, x11);
    o.z = pack_lo2(x00, x01);
    o.w = pack_lo2(x10, x11);
    dst[i] = o;
}

// ---------------- weight fragment prep (layer 1, K=27 padded to 32) ----------------
__global__ void prep_wfrag1(const float* __restrict__ w, uint4* __restrict__ dst)
{
    int i = blockIdx.x * 256 + threadIdx.x;
    if (i >= 512) return;
    int lane = i & 31;
    int nt   = (i >> 5) & 7;
    int ks   = i >> 8;
    int g = lane >> 2, l4 = lane & 3;
    int n  = nt * 8 + g;
    int k0 = ks * 16 + l4 * 2;
    float x[4];
#pragma unroll
    for (int j = 0; j < 4; j++) {
        int k = k0 + (j >> 1) * 8 + (j & 1);
        x[j] = (k < 27) ? w[k * 64 + n] : 0.f;
    }
    uint4 o;
    o.x = pack_hi2(x[0], x[1]);
    o.y = pack_hi2(x[2], x[3]);
    o.z = pack_lo2(x[0], x[1]);
    o.w = pack_lo2(x[2], x[3]);
    dst[i] = o;
}

// ---------------- layer 1: tensor conv via padded im2col (pair out) ------------
__global__ void __launch_bounds__(128)
conv1_tensor(const float* __restrict__ in_sup,
             const float* __restrict__ in_qry,
             const uint4* __restrict__ wfrag1,
             const float* __restrict__ cb, const float* __restrict__ gm,
             const float* __restrict__ bt, const float* __restrict__ mn,
             const float* __restrict__ vr,
             uint32_t* __restrict__ outh, uint32_t* __restrict__ outl)
{
    __shared__ float sWin[540];
    __shared__ uint4 sB[512];
    __shared__ float sS[64], sT[64];

    const int tid = threadIdx.x;
    const int wrp = tid >> 5;
    const int lane = tid & 31;
    const int g = lane >> 2, l4 = lane & 3;

    for (int i = tid; i < 512; i += 128) sB[i] = __ldg(wfrag1 + i);
    if (tid < 64) {
        float s = gm[tid] * rsqrtf(vr[tid] + 1e-3f);
        sS[tid] = s;
        sT[tid] = (cb[tid] - mn[tid]) * s + bt[tid];
    }
    __syncthreads();

    const int TR = 6, TC = 11, tpi = TR * TC;
    const int ntiles = NIMG * tpi;

    for (int tile = blockIdx.x; tile < ntiles; tile += gridDim.x) {
        const int img = tile / tpi;
        const int rem = tile - img * tpi;
        const int r0  = (rem / TC) * 16;
        const int c0  = (rem % TC) * 8;
        const float* base = (img < 400) ? (in_sup + (size_t)img * 84 * 84 * 3)
                                        : (in_qry + (size_t)(img - 400) * 84 * 84 * 3);

        for (int e = tid; e < 540; e += 128) {
            int cell = e / 3, ch = e - 3 * cell;
            int wr = cell / 10, wc = cell - 10 * wr;
            int gr = r0 - 1 + wr, gc = c0 - 1 + wc;
            float v = 0.f;
            if (gr >= 0 && gr < 84 && gc >= 0 && gc < 84)
                v = __ldg(base + ((size_t)gr * 84 + gc) * 3 + ch);
            sWin[e] = v;
        }
        __syncthreads();

        float d[2][8][4];
#pragma unroll
        for (int mt = 0; mt < 2; mt++)
#pragma unroll
            for (int nt = 0; nt < 8; nt++)
#pragma unroll
                for (int j = 0; j < 4; j++) d[mt][nt][j] = 0.f;

        auto l1v = [&](int prow, int k) -> float {
            if (k >= 27) return 0.f;
            int tap = k / 3, ch = k - 3 * tap;
            int ky = tap / 3, kx = tap - 3 * ky;
            return sWin[((prow + ky) * 10 + (g + kx)) * 3 + ch];
        };

#pragma unroll
        for (int ks = 0; ks < 2; ks++) {
            uint32_t ah[2][4], al[2][4];
#pragma unroll
            for (int mt = 0; mt < 2; mt++) {
                const int rb = 4 * wrp + 2 * mt;
                const int k0 = ks * 16 + 2 * l4;
                float x00 = l1v(rb,     k0),     x01 = l1v(rb,     k0 + 1);
                float x10 = l1v(rb + 1, k0),     x11 = l1v(rb + 1, k0 + 1);
                float x20 = l1v(rb,     k0 + 8), x21 = l1v(rb,     k0 + 9);
                float x30 = l1v(rb + 1, k0 + 8), x31 = l1v(rb + 1, k0 + 9);
                ah[mt][0] = pack_hi2(x00, x01); al[mt][0] = pack_lo2(x00, x01);
                ah[mt][1] = pack_hi2(x10, x11); al[mt][1] = pack_lo2(x10, x11);
                ah[mt][2] = pack_hi2(x20, x21); al[mt][2] = pack_lo2(x20, x21);
                ah[mt][3] = pack_hi2(x30, x31); al[mt][3] = pack_lo2(x30, x31);
            }
            uint4 b[8];
#pragma unroll
            for (int nt = 0; nt < 8; nt++) b[nt] = sB[(ks * 8 + nt) * 32 + lane];
#pragma unroll
            for (int nt = 0; nt < 8; nt++) {
                MMA_BF16(d[0][nt], ah[0], b[nt].x, b[nt].y);
                MMA_BF16(d[1][nt], ah[1], b[nt].x, b[nt].y);
            }
#pragma unroll
            for (int nt = 0; nt < 8; nt++) {
                MMA_BF16(d[0][nt], al[0], b[nt].x, b[nt].y);
                MMA_BF16(d[1][nt], al[1], b[nt].x, b[nt].y);
            }
#pragma unroll
            for (int nt = 0; nt < 8; nt++) {
                MMA_BF16(d[0][nt], ah[0], b[nt].z, b[nt].w);
                MMA_BF16(d[1][nt], ah[1], b[nt].z, b[nt].w);
            }
        }

#pragma unroll
        for (int mt = 0; mt < 2; mt++) {
            const int pr = (r0 >> 1) + 2 * wrp + mt;
            const int pc = (c0 >> 1) + (g >> 1);
            const bool valid = ((g & 1) == 0) && pr < 42 && pc < 42;
            const uint32_t obase = ((uint32_t)img * 42 + pr) * 42 + pc;
#pragma unroll
            for (int nt = 0; nt < 8; nt++) {
                const int oc = nt * 8 + l4 * 2;
                float s0 = sS[oc], s1 = sS[oc + 1];
                float t0 = sT[oc], t1 = sT[oc + 1];
                float v0 = fmaxf(fmaf(d[mt][nt][0], s0, t0), 0.f);
                float v1 = fmaxf(fmaf(d[mt][nt][1], s1, t1), 0.f);
                float v2 = fmaxf(fmaf(d[mt][nt][2], s0, t0), 0.f);
                float v3 = fmaxf(fmaf(d[mt][nt][3], s1, t1), 0.f);
                float m0 = fmaxf(v0, v2);
                float m1 = fmaxf(v1, v3);
                m0 = fmaxf(m0, __shfl_xor_sync(0xffffffffu, m0, 4));
                m1 = fmaxf(m1, __shfl_xor_sync(0xffffffffu, m1, 4));
                if (valid) {
                    uint32_t idx = obase * 32 + nt * 4 + l4;
                    outh[idx] = pack_hi2(m0, m1);
                    outl[idx] = pack_lo2(m0, m1);
                }
            }
        }
        __syncthreads();
    }
}

// ---------------- tensor conv (layers 2-4): ldmatrix A, L1 B, small smem --------
#define SMAH2  0                         // activation hi: 180*36*4 = 25920 B
#define SMAL2  25920                     // activation lo: 25920 B
#define SMC2   51840                     // BN consts: 512 B
#define CONV2_SMEM 52352

__global__ void __launch_bounds__(128)
conv_tensor(const uint4* __restrict__ inh, const uint4* __restrict__ inl,
            const uint4* __restrict__ wfrag,
            const float* __restrict__ cb, const float* __restrict__ gm,
            const float* __restrict__ bt, const float* __restrict__ mn,
            const float* __restrict__ vr,
            uint32_t* __restrict__ outh, uint32_t* __restrict__ outl,
            float* __restrict__ outf32,
            int H, int PH, int TR, int TC, int ntiles)
{
    extern __shared__ __align__(16) char smem[];
    const int tid = threadIdx.x;
    const int wrp = tid >> 5;
    const int lane = tid & 31;
    const int g = lane >> 2, l4 = lane & 3;

    if (tid < 64) {
        float s = gm[tid] * rsqrtf(vr[tid] + 1e-3f);
        float t = (cb[tid] - mn[tid]) * s + bt[tid];
        ((float*)(smem + SMC2))[tid] = s;
        ((float*)(smem + SMC2 + 256))[tid] = t;
    }
    __syncthreads();

    uint32_t* sAh = (uint32_t*)(smem + SMAH2);
    uint32_t* sAl = (uint32_t*)(smem + SMAL2);
    const float* sS = (const float*)(smem + SMC2);
    const float* sT = (const float*)(smem + SMC2 + 256);
    const int tpi = TR * TC;

    // 32-bit shared base addresses for ldmatrix
    const uint32_t shAh = (uint32_t)__cvta_generic_to_shared(sAh);
    const uint32_t shAl = (uint32_t)__cvta_generic_to_shared(sAl);
    // lane-dependent pieces (constant over tiles):
    const int tile_row_bit = (lane >> 3) & 1;       // +1 pixel row for a1/a3 tiles
    const uint32_t k_hi_off = (lane & 16) ? 16u : 0u; // +8 k-halves for a2/a3 tiles
    const int lcol = lane & 7;

    for (int tile = blockIdx.x; tile < ntiles; tile += gridDim.x) {
        const int img  = tile / tpi;
        const int rem  = tile - img * tpi;
        const int r0   = (rem / TC) * 16;
        const int c0   = (rem % TC) * 8;

        // ---- stage 18x10 window of 32 pairs: pure copies ----
        for (int e = tid; e < 180 * 8; e += 128) {
            int grp  = e & 7;
            int cell = e >> 3;
            int wr = cell / 10, wc = cell - 10 * wr;
            int gr = r0 - 1 + wr, gc = c0 - 1 + wc;
            uint4 vh = make_uint4(0, 0, 0, 0);
            uint4 vl = make_uint4(0, 0, 0, 0);
            if (gr >= 0 && gr < H && gc >= 0 && gc < H) {
                uint32_t idx = ((uint32_t)(img * H + gr) * H + gc) * 8 + grp;
                vh = __ldg(inh + idx);
                vl = __ldg(inl + idx);
            }
            *(uint4*)(sAh + cell * 36 + grp * 4) = vh;
            *(uint4*)(sAl + cell * 36 + grp * 4) = vl;
        }
        __syncthreads();

        float d[2][8][4];
#pragma unroll
        for (int mt = 0; mt < 2; mt++)
#pragma unroll
            for (int nt = 0; nt < 8; nt++)
#pragma unroll
                for (int j = 0; j < 4; j++) d[mt][nt][j] = 0.f;

        for (int tap = 0; tap < 9; tap++) {
            const int ky = tap / 3, kx = tap - 3 * (tap / 3);
            // per-lane ldmatrix row address for mt=0 (cell stride 144B)
            const uint32_t cell0 = (uint32_t)((4 * wrp + ky + tile_row_bit) * 10 + lcol + kx);
            const uint32_t aH0 = shAh + cell0 * 144u + k_hi_off;
            const uint32_t aH1 = aH0 + 2880u;       // mt=1: +2 pixel rows (20 cells)
            const uint32_t aL0 = shAl + cell0 * 144u + k_hi_off;
            const uint32_t aL1 = aL0 + 2880u;
#pragma unroll
            for (int ks = 0; ks < 4; ks++) {
                uint32_t ah[2][4], al[2][4];
                LDSM4(ah[0], aH0 + ks * 32u);
                LDSM4(ah[1], aH1 + ks * 32u);
                LDSM4(al[0], aL0 + ks * 32u);
                LDSM4(al[1], aL1 + ks * 32u);

                const uint4* wb = wfrag + ((tap * 4 + ks) * 8) * 32 + lane;
                uint4 b[8];
#pragma unroll
                for (int nt = 0; nt < 8; nt++) b[nt] = __ldg(wb + nt * 32);
#pragma unroll
                for (int nt = 0; nt < 8; nt++) {
                    MMA_BF16(d[0][nt], ah[0], b[nt].x, b[nt].y);   // hi*hi
                    MMA_BF16(d[1][nt], ah[1], b[nt].x, b[nt].y);
                }
#pragma unroll
                for (int nt = 0; nt < 8; nt++) {
                    MMA_BF16(d[0][nt], al[0], b[nt].x, b[nt].y);   // lo*hi
                    MMA_BF16(d[1][nt], al[1], b[nt].x, b[nt].y);
                }
#pragma unroll
                for (int nt = 0; nt < 8; nt++) {
                    MMA_BF16(d[0][nt], ah[0], b[nt].z, b[nt].w);   // hi*lo
                    MMA_BF16(d[1][nt], ah[1], b[nt].z, b[nt].w);
                }
            }
        }

        // ---- BN + ReLU + 2x2 maxpool + store (pair or fp32) ----
#pragma unroll
        for (int mt = 0; mt < 2; mt++) {
            const int pr = (r0 >> 1) + 2 * wrp + mt;
            const int pc = (c0 >> 1) + (g >> 1);
            const bool valid = ((g & 1) == 0) && pr < PH && pc < PH;
            const uint32_t obase = ((uint32_t)img * PH + pr) * PH + pc;
#pragma unroll
            for (int nt = 0; nt < 8; nt++) {
                const int oc = nt * 8 + l4 * 2;
                float s0 = sS[oc], s1 = sS[oc + 1];
                float t0 = sT[oc], t1 = sT[oc + 1];
                float v0 = fmaxf(fmaf(d[mt][nt][0], s0, t0), 0.f);
                float v1 = fmaxf(fmaf(d[mt][nt][1], s1, t1), 0.f);
                float v2 = fmaxf(fmaf(d[mt][nt][2], s0, t0), 0.f);
                float v3 = fmaxf(fmaf(d[mt][nt][3], s1, t1), 0.f);
                float m0 = fmaxf(v0, v2);
                float m1 = fmaxf(v1, v3);
                m0 = fmaxf(m0, __shfl_xor_sync(0xffffffffu, m0, 4));
                m1 = fmaxf(m1, __shfl_xor_sync(0xffffffffu, m1, 4));
                if (valid) {
                    if (outf32) {
                        *(float2*)(outf32 + (size_t)obase * 64 + oc) = make_float2(m0, m1);
                    } else {
                        uint32_t idx = obase * 32 + nt * 4 + l4;
                        outh[idx] = pack_hi2(m0, m1);
                        outl[idx] = pack_lo2(m0, m1);
                    }
                }
            }
        }
        __syncthreads();
    }
}

// ---------------- x @ Wk + bias ----------------
__global__ void xwk_gemm(const float* __restrict__ emb,
                         const float* __restrict__ Wk,
                         const float* __restrict__ bias,
                         float* __restrict__ outp)
{
    int idx = blockIdx.x * blockDim.x + threadIdx.x;
    if (idx >= NIMG * GATES) return;
    int u = idx & (GATES - 1);
    int n = idx >> 7;
    const float* e = emb + (size_t)n * DEMB;
    float acc = __ldg(bias + u);
#pragma unroll 4
    for (int k = 0; k < DEMB; k += 4) {
        float4 ev = *reinterpret_cast<const float4*>(e + k);
        acc = fmaf(ev.x, __ldg(Wk + (size_t)(k + 0) * GATES + u), acc);
        acc = fmaf(ev.y, __ldg(Wk + (size_t)(k + 1) * GATES + u), acc);
        acc = fmaf(ev.z, __ldg(Wk + (size_t)(k + 2) * GATES + u), acc);
        acc = fmaf(ev.w, __ldg(Wk + (size_t)(k + 3) * GATES + u), acc);
    }
    outp[idx] = acc;
}

// ---------------- LSTM chains over the BATCH axis ----------------
__device__ __forceinline__ float sigm(float x) { return 1.f / (1.f + expf(-x)); }

__global__ void lstm_chains(const float* __restrict__ xwkf,
                            const float* __restrict__ xwkb,
                            const float* __restrict__ Wrf,
                            const float* __restrict__ Wrb,
                            float* __restrict__ sf, float* __restrict__ sb2,
                            float* __restrict__ qf, float* __restrict__ qb)
{
    __shared__ float wr[HL * GATES];
    __shared__ float h[HL], c[HL], z[GATES];

    const int u     = threadIdx.x;
    const int chain = blockIdx.x;
    const int dir   = blockIdx.y;

    const float* xwk = dir ? xwkb : xwkf;
    const float* Wr  = dir ? Wrb  : Wrf;
    float* outp = (chain < NS) ? (dir ? sb2 : sf) : (dir ? qb : qf);
    const int cpos = (chain < NS) ? chain : (chain - NS);

#pragma unroll
    for (int k = 0; k < HL; k++) wr[k * GATES + u] = Wr[k * GATES + u];
    if (u < HL) { h[u] = 0.f; c[u] = 0.f; }
    __syncthreads();

    for (int t = 0; t < NB; t++) {
        const int b = dir ? (NB - 1 - t) : t;
        const int row = (chain < NS) ? (b * NS + cpos) : (400 + b * NQ + cpos);
        float acc = __ldg(xwk + (size_t)row * GATES + u);
#pragma unroll
        for (int k = 0; k < HL; k++) acc = fmaf(h[k], wr[k * GATES + u], acc);
        z[u] = acc;
        __syncthreads();
        if (u < HL) {
            float zi = z[u], zf = z[HL + u], zg = z[2 * HL + u], zo = z[3 * HL + u];
            float cc = sigm(zf) * c[u] + sigm(zi) * tanhf(zg);
            float hh = sigm(zo) * tanhf(cc);
            c[u] = cc; h[u] = hh;
            outp[(cpos * NB + b) * HL + u] = hh;
        }
        __syncthreads();
    }
}

// ---------------- attention readout + CE + accuracy ----------------
__global__ void readout(const float* __restrict__ sf, const float* __restrict__ sb2,
                        const float* __restrict__ qf, const float* __restrict__ qb,
                        const int* __restrict__ ysup, const int* __restrict__ yqry,
                        float* __restrict__ out)
{
    __shared__ float ce_sm[NQ * NB];
    __shared__ float corr_sm[NQ * NB];
    const int t = threadIdx.x;

    if (t < NQ * NB) {
        const int q = t / NB, b = t % NB;
        float vf[HL], vb[HL];
#pragma unroll
        for (int j = 0; j < HL; j++) {
            vf[j] = qf[(q * NB + b) * HL + j];
            vb[j] = qb[(q * NB + b) * HL + j];
        }
        float scores[NS];
        float mx = -1e30f;
        for (int s = 0; s < NS; s++) {
            float dot = 0.f, nrm = 0.f;
#pragma unroll
            for (int j = 0; j < HL; j++) {
                float a = sf[(s * NB + b) * HL + j];
                dot = fmaf(vf[j], a, dot); nrm = fmaf(a, a, nrm);
            }
#pragma unroll
            for (int j = 0; j < HL; j++) {
                float a = sb2[(s * NB + b) * HL + j];
                dot = fmaf(vb[j], a, dot); nrm = fmaf(a, a, nrm);
            }
            float sc = dot * rsqrtf(fmaxf(nrm, 1e-10f));
            scores[s] = sc; mx = fmaxf(mx, sc);
        }
        float sum = 0.f;
        for (int s = 0; s < NS; s++) { scores[s] = expf(scores[s] - mx); sum += scores[s]; }
        float inv = 1.f / sum;
        float preds[NWAY] = {0.f, 0.f, 0.f, 0.f, 0.f};
        for (int s = 0; s < NS; s++) preds[ysup[b * NS + s]] += scores[s] * inv;

        float psum = 0.f;
        for (int w = 0; w < NWAY; w++) psum += preds[w];
        const int yq = yqry[b * NQ + q];
        float pv = preds[yq] / psum;
        pv = fminf(fmaxf(pv, 1e-7f), 1.f - 1e-7f);
        ce_sm[t] = -logf(pv);

        int am = 0; float bv = preds[0];
        for (int w = 1; w < NWAY; w++) if (preds[w] > bv) { bv = preds[w]; am = w; }
        corr_sm[t] = (am == yq) ? 1.f : 0.f;
    }
    __syncthreads();
    if (t < NB) {
        float s = 0.f;
        for (int q = 0; q < NQ; q++) s += ce_sm[q * NB + t];
        out[t] = s / (float)NQ;
    }
    if (t == 16) {
        float s = 0.f;
        for (int i = 0; i < NQ * NB; i++) s += corr_sm[i];
        out[16] = s / (float)(NQ * NB);
    }
}

// ---------------- launch ----------------
extern "C" void kernel_launch(void* const* d_in, const int* in_sizes, int n_in,
                              void* d_out, int out_size)
{
    const float* xs = (const float*)d_in[0];
    const float* xq = (const float*)d_in[1];
    const int*   ys = (const int*)  d_in[2];
    const int*   yq = (const int*)  d_in[3];
    const float* w1 = (const float*)d_in[4];
    const float* w2 = (const float*)d_in[5];
    const float* w3 = (const float*)d_in[6];
    const float* w4 = (const float*)d_in[7];
    const float* cb = (const float*)d_in[8];
    const float* gm = (const float*)d_in[9];
    const float* bt = (const float*)d_in[10];
    const float* mn = (const float*)d_in[11];
    const float* vr = (const float*)d_in[12];
    const float* fk = (const float*)d_in[13];
    const float* fr = (const float*)d_in[14];
    const float* fb = (const float*)d_in[15];
    const float* bk = (const float*)d_in[16];
    const float* br = (const float*)d_in[17];
    const float* bb = (const float*)d_in[18];

    uint32_t *b1h, *b1l, *b2h, *b2l, *b3h, *b3l;
    float *emb, *xwkf, *xwkb, *sf, *sb, *qf, *qb;
    uint4 *wfrag, *wfrag1;
    cudaGetSymbolAddress((void**)&b1h, g_b1h);
    cudaGetSymbolAddress((void**)&b1l, g_b1l);
    cudaGetSymbolAddress((void**)&b2h, g_b2h);
    cudaGetSymbolAddress((void**)&b2l, g_b2l);
    cudaGetSymbolAddress((void**)&b3h, g_b3h);
    cudaGetSymbolAddress((void**)&b3l, g_b3l);
    cudaGetSymbolAddress((void**)&emb,  g_emb);
    cudaGetSymbolAddress((void**)&xwkf, g_xwkf);
    cudaGetSymbolAddress((void**)&xwkb, g_xwkb);
    cudaGetSymbolAddress((void**)&sf,   g_sf);
    cudaGetSymbolAddress((void**)&sb,   g_sb);
    cudaGetSymbolAddress((void**)&qf,   g_qf);
    cudaGetSymbolAddress((void**)&qb,   g_qb);
    cudaGetSymbolAddress((void**)&wfrag, g_wfrag);
    cudaGetSymbolAddress((void**)&wfrag1, g_wfrag1);

    cudaFuncSetAttribute(conv_tensor, cudaFuncAttributeMaxDynamicSharedMemorySize, CONV2_SMEM);

    // weight fragment prep (tiny)
    prep_wfrag1<<<2, 256>>>(w1, wfrag1);
    prep_wfrag<<<36, 256>>>(w2, wfrag + 0 * 9216);
    prep_wfrag<<<36, 256>>>(w3, wfrag + 1 * 9216);
    prep_wfrag<<<36, 256>>>(w4, wfrag + 2 * 9216);

    // layer 1: tensor path, high-occupancy grid, pair output
    conv1_tensor<<<1184, 128>>>(xs, xq, wfrag1,
        cb + 0, gm + 0, bt + 0, mn + 0, vr + 0, b1h, b1l);

    // layers 2-4: ldmatrix A-frag loads, B via L1, 3-4 CTAs/SM
    conv_tensor<<<592, 128, CONV2_SMEM>>>(
        (const uint4*)b1h, (const uint4*)b1l, wfrag + 0 * 9216,
        cb + 64,  gm + 64,  bt + 64,  mn + 64,  vr + 64,
        b2h, b2l, nullptr, 42, 21, 3, 6, 640 * 18);
    conv_tensor<<<592, 128, CONV2_SMEM>>>(
        (const uint4*)b2h, (const uint4*)b2l, wfrag + 1 * 9216,
        cb + 128, gm + 128, bt + 128, mn + 128, vr + 128,
        b3h, b3l, nullptr, 21, 10, 2, 3, 640 * 6);
    conv_tensor<<<592, 128, CONV2_SMEM>>>(
        (const uint4*)b3h, (const uint4*)b3l, wfrag + 2 * 9216,
        cb + 192, gm + 192, bt + 192, mn + 192, vr + 192,
        nullptr, nullptr, emb, 10, 5, 1, 2, 640 * 2);

    // FCE input projections
    xwk_gemm<<<(NIMG * GATES + 255) / 256, 256>>>(emb, fk, fb, xwkf);
    xwk_gemm<<<(NIMG * GATES + 255) / 256, 256>>>(emb, bk, bb, xwkb);

    // FCE chains (recurrence over the batch axis)
    lstm_chains<<<dim3(40, 2), GATES>>>(xwkf, xwkb, fr, br, sf, sb, qf, qb);

    // attention + CE + acc
    readout<<<1, 256>>>(sf, sb, qf, qb, ys, yq, (float*)d_out);
}